// round 14
// baseline (speedup 1.0000x reference)
#include <cuda_runtime.h>
#include <cuda_bf16.h>
#include <cuda_fp16.h>
#include <stdint.h>
#include <math.h>

#define H 128
#define NE_MAX 50000

typedef unsigned int uint;
typedef unsigned short u16;

// ---------------- device scratch (allocation-free rule) ----------------
__device__ u16   g_eh [NE_MAX * H];
__device__ u16   g_el [NE_MAX * H];
__device__ u16   g_e2h[NE_MAX * H];
__device__ u16   g_e2l[NE_MAX * H];
__device__ u16   g_hh [NE_MAX * H];
__device__ u16   g_hl [NE_MAX * H];
__device__ u16   g_Pq [NE_MAX * H];      // fp16 P
__device__ u16   g_Qq [NE_MAX * H];      // fp16 Q
__device__ float g_agg[NE_MAX * H];
__device__ int   g_deg[NE_MAX];
__device__ float g_bc [3 * H];
#define WSCRATCH 368640
__device__ u16 g_wh[WSCRATCH];
__device__ u16 g_wl[WSCRATCH];

// transposed/split weight offsets (elements)
#define OFF_ENC1 0
#define OFF_ENC2 8192
#define OFF_L(l)   (24576 + (l) * 98304)
#define OFF_W1T(l) (OFF_L(l))
#define OFF_W1B(l) (OFF_L(l) + 16384)
#define OFF_WC(l)  (OFF_L(l) + 32768)
#define OFF_U1T(l) (OFF_L(l) + 49152)
#define OFF_UW2(l) (OFF_L(l) + 81920)
#define OFF_P1T 319488
#define OFF_P1B 335872
#define OFF_P2  352256

// ---- single-GEMM smem layout ----
#define WROW 68
#define WH_W 0
#define WL_W 8704
#define ABASE 17408
#define ABUF  8704
#define AHALF 4352
#define CTRL_W 34816
#define SMEM_WORDS 35104
#define SMEM_BYTES (SMEM_WORDS * 4)

// ---- dual-GEMM smem layout ----
#define D_W1H 0
#define D_W1L 8704
#define D_W2H 17408
#define D_W2L 26112
#define D_ABASE 34816
#define D_ABUF  8704
#define D_AHALF 4352
#define D_SMEM_WORDS 52224
#define D_SMEM_BYTES (D_SMEM_WORDS * 4)

// ---------------- helpers ----------------
__device__ __forceinline__ uint phi(float a, float b) {
    return (uint)__bfloat16_as_ushort(__float2bfloat16_rn(a))
         | ((uint)__bfloat16_as_ushort(__float2bfloat16_rn(b)) << 16);
}
__device__ __forceinline__ uint plo(float a, float b) {
    float ah = __bfloat162float(__float2bfloat16_rn(a));
    float bh = __bfloat162float(__float2bfloat16_rn(b));
    return phi(a - ah, b - bh);
}
__device__ __forceinline__ uint h2u(float a, float b) {
    __half2 h = __floats2half2_rn(a, b);
    return *(uint*)&h;
}
__device__ __forceinline__ float2 u2f(uint u) {
    return __half22float2(*(const __half2*)&u);
}
__device__ __forceinline__ uint smem_u32(const void* p) {
    uint a;
    asm("{ .reg .u64 t; cvta.to.shared.u64 t, %1; cvt.u32.u64 %0, t; }" : "=r"(a) : "l"(p));
    return a;
}
__device__ __forceinline__ void cpa16(uint dst, const void* src) {
    asm volatile("cp.async.cg.shared.global [%0], [%1], 16;" :: "r"(dst), "l"(src));
}
#define CPA_COMMIT() asm volatile("cp.async.commit_group;" ::: "memory")
#define CPA_WAIT(n)  asm volatile("cp.async.wait_group %0;" :: "n"(n) : "memory")

__device__ __forceinline__ void mma_bf(float* c, uint a0, uint a1, uint a2, uint a3,
                                       uint b0, uint b1) {
    asm volatile(
        "mma.sync.aligned.m16n8k16.row.col.f32.bf16.bf16.f32 "
        "{%0,%1,%2,%3},{%4,%5,%6,%7},{%8,%9},{%0,%1,%2,%3};"
        : "+f"(c[0]), "+f"(c[1]), "+f"(c[2]), "+f"(c[3])
        : "r"(a0), "r"(a1), "r"(a2), "r"(a3), "r"(b0), "r"(b1));
}
__device__ __forceinline__ void ldsm4(uint& r0, uint& r1, uint& r2, uint& r3, uint addr) {
    asm volatile("ldmatrix.sync.aligned.m8n8.x4.shared.b16 {%0,%1,%2,%3}, [%4];"
        : "=r"(r0), "=r"(r1), "=r"(r2), "=r"(r3) : "r"(addr));
}

// warp tile 16x32 via ldmatrix; 16 warps = 4(M) x 4(N); M-tile 64, N 128
template <int NK>
__device__ __forceinline__ void gemm_core_lm(uint sb, int aH, int aL, int wH, int wL,
                                             float acc[4][4], int wm, int wn, int lane) {
    const int l7 = lane & 7, lm = lane >> 3;
    const int radd = (lm & 1) * 8;
    const int koff = (lm >> 1) * 4;
    uint aBh  = sb + ((uint)(aH + (wm + l7 + radd) * WROW + koff) << 2);
    uint aBl  = sb + ((uint)(aL + (wm + l7 + radd) * WROW + koff) << 2);
    uint bBh0 = sb + ((uint)(wH + (wn + l7 + radd) * WROW + koff) << 2);
    uint bBl0 = sb + ((uint)(wL + (wn + l7 + radd) * WROW + koff) << 2);
    uint bBh1 = bBh0 + 16 * WROW * 4;
    uint bBl1 = bBl0 + 16 * WROW * 4;
#pragma unroll
    for (int ks = 0; ks < NK; ks++) {
        uint ko = ks * 32;
        uint ah0, ah1, ah2, ah3, al0, al1, al2, al3;
        ldsm4(ah0, ah1, ah2, ah3, aBh + ko);
        ldsm4(al0, al1, al2, al3, aBl + ko);
        uint p0, p1, p2, p3, q0, q1, q2, q3;
        ldsm4(p0, p1, p2, p3, bBh0 + ko);
        ldsm4(q0, q1, q2, q3, bBh1 + ko);
        uint u0, u1, u2, u3, v0, v1, v2, v3;
        ldsm4(u0, u1, u2, u3, bBl0 + ko);
        ldsm4(v0, v1, v2, v3, bBl1 + ko);
        mma_bf(acc[0], ah0, ah1, ah2, ah3, p0, p2);
        mma_bf(acc[1], ah0, ah1, ah2, ah3, p1, p3);
        mma_bf(acc[2], ah0, ah1, ah2, ah3, q0, q2);
        mma_bf(acc[3], ah0, ah1, ah2, ah3, q1, q3);
        mma_bf(acc[0], ah0, ah1, ah2, ah3, u0, u2);
        mma_bf(acc[1], ah0, ah1, ah2, ah3, u1, u3);
        mma_bf(acc[2], ah0, ah1, ah2, ah3, v0, v2);
        mma_bf(acc[3], ah0, ah1, ah2, ah3, v1, v3);
        mma_bf(acc[0], al0, al1, al2, al3, p0, p2);
        mma_bf(acc[1], al0, al1, al2, al3, p1, p3);
        mma_bf(acc[2], al0, al1, al2, al3, q0, q2);
        mma_bf(acc[3], al0, al1, al2, al3, q1, q3);
    }
}

// fused dual-weight core: one A stream, two weight sets, interleaved acc1/acc2
template <int NK>
__device__ __forceinline__ void gemm_dual_lm(uint sb, int aH, int aL,
                                             int w1H, int w1L, int w2H, int w2L,
                                             float acc1[4][4], float acc2[4][4],
                                             int wm, int wn, int lane) {
    const int l7 = lane & 7, lm = lane >> 3;
    const int radd = (lm & 1) * 8;
    const int koff = (lm >> 1) * 4;
    uint aBh  = sb + ((uint)(aH + (wm + l7 + radd) * WROW + koff) << 2);
    uint aBl  = sb + ((uint)(aL + (wm + l7 + radd) * WROW + koff) << 2);
    uint b1h0 = sb + ((uint)(w1H + (wn + l7 + radd) * WROW + koff) << 2);
    uint b1l0 = sb + ((uint)(w1L + (wn + l7 + radd) * WROW + koff) << 2);
    uint b2h0 = sb + ((uint)(w2H + (wn + l7 + radd) * WROW + koff) << 2);
    uint b2l0 = sb + ((uint)(w2L + (wn + l7 + radd) * WROW + koff) << 2);
    const uint HS = 16 * WROW * 4;
#pragma unroll
    for (int ks = 0; ks < NK; ks++) {
        uint ko = ks * 32;
        uint ah0, ah1, ah2, ah3, al0, al1, al2, al3;
        ldsm4(ah0, ah1, ah2, ah3, aBh + ko);
        ldsm4(al0, al1, al2, al3, aBl + ko);
        uint p0, p1, p2, p3, q0, q1, q2, q3;      // W1 hi halves
        ldsm4(p0, p1, p2, p3, b1h0 + ko);
        ldsm4(q0, q1, q2, q3, b1h0 + HS + ko);
        uint r0, r1, r2, r3, s0, s1, s2, s3;      // W2 hi halves
        ldsm4(r0, r1, r2, r3, b2h0 + ko);
        ldsm4(s0, s1, s2, s3, b2h0 + HS + ko);
        // hi*hi interleaved
        mma_bf(acc1[0], ah0, ah1, ah2, ah3, p0, p2);
        mma_bf(acc2[0], ah0, ah1, ah2, ah3, r0, r2);
        mma_bf(acc1[1], ah0, ah1, ah2, ah3, p1, p3);
        mma_bf(acc2[1], ah0, ah1, ah2, ah3, r1, r3);
        mma_bf(acc1[2], ah0, ah1, ah2, ah3, q0, q2);
        mma_bf(acc2[2], ah0, ah1, ah2, ah3, s0, s2);
        mma_bf(acc1[3], ah0, ah1, ah2, ah3, q1, q3);
        mma_bf(acc2[3], ah0, ah1, ah2, ah3, s1, s3);
        // lo(A)*hi(B)
        mma_bf(acc1[0], al0, al1, al2, al3, p0, p2);
        mma_bf(acc2[0], al0, al1, al2, al3, r0, r2);
        mma_bf(acc1[1], al0, al1, al2, al3, p1, p3);
        mma_bf(acc2[1], al0, al1, al2, al3, r1, r3);
        mma_bf(acc1[2], al0, al1, al2, al3, q0, q2);
        mma_bf(acc2[2], al0, al1, al2, al3, s0, s2);
        mma_bf(acc1[3], al0, al1, al2, al3, q1, q3);
        mma_bf(acc2[3], al0, al1, al2, al3, s1, s3);
        // hi(A)*lo(B): reuse regs for lo weight fragments
        ldsm4(p0, p1, p2, p3, b1l0 + ko);
        ldsm4(q0, q1, q2, q3, b1l0 + HS + ko);
        ldsm4(r0, r1, r2, r3, b2l0 + ko);
        ldsm4(s0, s1, s2, s3, b2l0 + HS + ko);
        mma_bf(acc1[0], ah0, ah1, ah2, ah3, p0, p2);
        mma_bf(acc2[0], ah0, ah1, ah2, ah3, r0, r2);
        mma_bf(acc1[1], ah0, ah1, ah2, ah3, p1, p3);
        mma_bf(acc2[1], ah0, ah1, ah2, ah3, r1, r3);
        mma_bf(acc1[2], ah0, ah1, ah2, ah3, q0, q2);
        mma_bf(acc2[2], ah0, ah1, ah2, ah3, s0, s2);
        mma_bf(acc1[3], ah0, ah1, ah2, ah3, q1, q3);
        mma_bf(acc2[3], ah0, ah1, ah2, ah3, s1, s3);
    }
}

template <int NK>
__device__ __forceinline__ void load_weights(uint* sm, int dH, int dL,
                                             const u16* Wth, const u16* Wtl, int tid) {
    const int nv = 128 * NK * 2;
    const uint4* sh = (const uint4*)Wth;
    const uint4* sl = (const uint4*)Wtl;
    for (int i = tid; i < nv; i += 512) {
        int n = i / (NK * 2), q = i % (NK * 2);
        *(uint4*)(sm + dH + n * WROW + q * 4) = sh[i];
        *(uint4*)(sm + dL + n * WROW + q * 4) = sl[i];
    }
}

// ---------------- small kernels ----------------
__global__ void deg_kernel(const int* __restrict__ dst, int na, int* __restrict__ deg) {
    int i = blockIdx.x * blockDim.x + threadIdx.x;
    if (i < na) atomicAdd(&deg[dst[i]], 1);
}

struct PJobs {
    const float* W[20];
    int rowoff[20], K[20], off[20], start[20];
    int njobs, total;
};
__global__ void prep_all(PJobs j) {
    int i = blockIdx.x * 256 + threadIdx.x;
    if (i >= j.total) return;
    int a = 0;
    while (a + 1 < j.njobs && i >= j.start[a + 1]) a++;
    int e = i - j.start[a];
    int K = j.K[a];
    int n = e / K, k = e % K;
    float v = j.W[a][(size_t)(j.rowoff[a] + k) * 128 + n];
    __nv_bfloat16 h = __float2bfloat16_rn(v);
    g_wh[j.off[a] + e] = __bfloat16_as_ushort(h);
    g_wl[j.off[a] + e] = __bfloat16_as_ushort(__float2bfloat16_rn(v - __bfloat162float(h)));
}

__global__ void compprep(const float* __restrict__ upd_W1,
                         const float* __restrict__ msg_W2,
                         const float* __restrict__ msg_b2,
                         const float* __restrict__ upd_b1) {
    int b = blockIdx.x;
    if (b < 192) {
        int l = b >> 6;
        int i = (b & 63) * 256 + threadIdx.x;
        int o = i & 127, h = i >> 7;
        const float* W2  = msg_W2 + (size_t)l * 16384;
        const float* U1b = upd_W1 + (size_t)l * 32768 + 16384;
        float s = 0.f;
        for (int a2 = 0; a2 < 128; a2++) s += W2[h * 128 + a2] * U1b[a2 * 128 + o];
        int li = OFF_WC(l) + o * 128 + h;
        __nv_bfloat16 hh = __float2bfloat16_rn(s);
        g_wh[li] = __bfloat16_as_ushort(hh);
        g_wl[li] = __bfloat16_as_ushort(__float2bfloat16_rn(s - __bfloat162float(hh)));
    } else if (b < 195) {
        int l = b - 192;
        int o = threadIdx.x;
        if (o < 128) {
            const float* U1b = upd_W1 + (size_t)l * 32768 + 16384;
            const float* b2  = msg_b2 + (size_t)l * 128;
            float s = upd_b1[l * 128 + o];
            for (int a2 = 0; a2 < 128; a2++) s += b2[a2] * U1b[a2 * 128 + o];
            g_bc[l * 128 + o] = s;
        }
    }
}

// pair hidden aggregation: Hagg[dst] += ReLU(P[dst] + Q[src] + b1)  (P,Q fp16)
__global__ __launch_bounds__(256) void msum(const u16* __restrict__ P,
                                            const u16* __restrict__ Q,
                                            const float* __restrict__ b1,
                                            const int* __restrict__ dst,
                                            const int* __restrict__ src,
                                            float* __restrict__ Hagg, int na) {
    int team = threadIdx.x >> 7, col = threadIdx.x & 127;
    int p0 = blockIdx.x * 128 + team * 64;
    if (p0 >= na) return;
    float bias = __ldg(&b1[col]);
    float sum = 0.f, pv = 0.f;
    int cur = -1;
    for (int base = 0; base < 64; base += 8) {
        int dd[8], ss[8];
#pragma unroll
        for (int j = 0; j < 8; j++) {
            int a = p0 + base + j;
            bool v = a < na;
            dd[j] = v ? __ldg(&dst[a]) : -1;
            ss[j] = v ? __ldg(&src[a]) : 0;
        }
        float qv[8];
#pragma unroll
        for (int j = 0; j < 8; j++)
            qv[j] = __half2float(((const __half*)Q)[(size_t)ss[j] * H + col]);
#pragma unroll
        for (int j = 0; j < 8; j++) {
            if (dd[j] != cur) {
                if (cur >= 0) atomicAdd(&Hagg[(size_t)cur * H + col], sum);
                cur = dd[j];
                sum = 0.f;
                if (cur >= 0)
                    pv = __half2float(((const __half*)P)[(size_t)cur * H + col]) + bias;
            }
            if (dd[j] >= 0) sum += fmaxf(pv + qv[j], 0.f);
        }
    }
    if (cur >= 0) atomicAdd(&Hagg[(size_t)cur * H + col], sum);
}

// ---------------- fused encoder ----------------
__global__ __launch_bounds__(512, 1)
void gk_enc(const float* __restrict__ feat,
            const u16* __restrict__ W1h_, const u16* __restrict__ W1l_,
            const u16* __restrict__ W2h_, const u16* __restrict__ W2l_,
            const float* __restrict__ b1, const float* __restrict__ b2,
            u16* __restrict__ obh, u16* __restrict__ obl,
            int nrows, int ntiles)
{
    extern __shared__ uint sm[];
    const int tid = threadIdx.x;
    const int lane = tid & 31, w = tid >> 5;
    const int wm = (w & 3) * 16, wn = (w >> 2) * 32;
    const uint sb = smem_u32(sm);
    const int HID = D_ABASE + D_ABUF;

    load_weights<4>(sm, D_W1H, D_W1L, W1h_, W1l_, tid);
    load_weights<8>(sm, D_W2H, D_W2L, W2h_, W2l_, tid);

    const int r8 = tid >> 3, c8 = tid & 7;
    const int lg = lane >> 2, lt = lane & 3;

    for (int t = blockIdx.x; t < ntiles; t += gridDim.x) {
        const int t0 = t * 64;
        __syncthreads();
        {
            int gr = t0 + r8;
            int rr = (gr < nrows) ? gr : 0;
            const float4* s = (const float4*)(feat + (size_t)rr * 64) + c8 * 2;
            int base = D_ABASE + r8 * WROW + c8 * 4;
#pragma unroll
            for (int q = 0; q < 2; q++) {
                float4 v = s[q];
                *(uint2*)(sm + base + 2 * q)           = make_uint2(phi(v.x, v.y), phi(v.z, v.w));
                *(uint2*)(sm + base + D_AHALF + 2 * q) = make_uint2(plo(v.x, v.y), plo(v.z, v.w));
            }
        }
        __syncthreads();

        float acc[4][4];
#pragma unroll
        for (int nf = 0; nf < 4; nf++)
#pragma unroll
            for (int q = 0; q < 4; q++) acc[nf][q] = 0.f;
        gemm_core_lm<4>(sb, D_ABASE, D_ABASE + D_AHALF, D_W1H, D_W1L, acc, wm, wn, lane);

#pragma unroll
        for (int nf = 0; nf < 4; nf++) {
            int row = wm + lg;
            int col = wn + nf * 8 + lt * 2;
            float b0 = __ldg(&b1[col]), b1v = __ldg(&b1[col + 1]);
            float v0 = fmaxf(acc[nf][0] + b0, 0.f);
            float v1 = fmaxf(acc[nf][1] + b1v, 0.f);
            float v2 = fmaxf(acc[nf][2] + b0, 0.f);
            float v3 = fmaxf(acc[nf][3] + b1v, 0.f);
            int wi = col >> 1;
            sm[HID + row * WROW + wi]                 = phi(v0, v1);
            sm[HID + D_AHALF + row * WROW + wi]       = plo(v0, v1);
            sm[HID + (row + 8) * WROW + wi]           = phi(v2, v3);
            sm[HID + D_AHALF + (row + 8) * WROW + wi] = plo(v2, v3);
        }
        __syncthreads();

#pragma unroll
        for (int nf = 0; nf < 4; nf++)
#pragma unroll
            for (int q = 0; q < 4; q++) acc[nf][q] = 0.f;
        gemm_core_lm<8>(sb, HID, HID + D_AHALF, D_W2H, D_W2L, acc, wm, wn, lane);

#pragma unroll
        for (int nf = 0; nf < 4; nf++) {
            int row = wm + lg;
            int col = wn + nf * 8 + lt * 2;
            int g0 = t0 + row, g1 = g0 + 8;
            float b0 = __ldg(&b2[col]), b1v = __ldg(&b2[col + 1]);
            float v0 = acc[nf][0] + b0, v1 = acc[nf][1] + b1v;
            float v2 = acc[nf][2] + b0, v3 = acc[nf][3] + b1v;
            int wi = col >> 1;
            if (g0 < nrows) {
                ((uint*)obh)[(size_t)g0 * 64 + wi] = phi(v0, v1);
                ((uint*)obl)[(size_t)g0 * 64 + wi] = plo(v0, v1);
            }
            if (g1 < nrows) {
                ((uint*)obh)[(size_t)g1 * 64 + wi] = phi(v2, v3);
                ((uint*)obl)[(size_t)g1 * 64 + wi] = plo(v2, v3);
            }
        }
    }
}

// ---------------- single GEMM (bf16 in, cp.async double-buffer), bias+ReLU -> bf16 ----------------
__global__ __launch_bounds__(512, 1)
void gk_plain(const u16* __restrict__ Aph, const u16* __restrict__ Apl,
              const u16* __restrict__ Wth, const u16* __restrict__ Wtl,
              const float* __restrict__ bias,
              u16* __restrict__ obh, u16* __restrict__ obl,
              int nrows, int ntiles)
{
    extern __shared__ uint sm[];
    const int tid = threadIdx.x;
    const int lane = tid & 31, w = tid >> 5;
    const int wm = (w & 3) * 16, wn = (w >> 2) * 32;
    const uint sb = smem_u32(sm);

    load_weights<8>(sm, WH_W, WL_W, Wth, Wtl, tid);

    const int r8 = tid >> 3, c8 = tid & 7;

    auto fill_async = [&](int t, int p) {
        int gr = t * 64 + r8;
        int rr = (gr < nrows) ? gr : 0;
        const char* shp = (const char*)(Aph + (size_t)rr * H) + c8 * 16;
        const char* slp = (const char*)(Apl + (size_t)rr * H) + c8 * 16;
        uint dh = sb + (ABASE + p * ABUF + r8 * WROW + c8 * 4) * 4;
        uint dl = dh + AHALF * 4;
        cpa16(dh, shp);        cpa16(dh + 128, shp + 128);
        cpa16(dl, slp);        cpa16(dl + 128, slp + 128);
        CPA_COMMIT();
    };

    int p = 0;
    fill_async(blockIdx.x < ntiles ? blockIdx.x : 0, 0);

    for (int t = blockIdx.x; t < ntiles; t += gridDim.x) {
        __syncthreads();
        int tn = t + gridDim.x;
        fill_async(tn < ntiles ? tn : t, p ^ 1);
        CPA_WAIT(1);
        __syncthreads();

        float acc[4][4];
#pragma unroll
        for (int nf = 0; nf < 4; nf++)
#pragma unroll
            for (int q = 0; q < 4; q++) acc[nf][q] = 0.f;
        int aH = ABASE + p * ABUF;
        gemm_core_lm<8>(sb, aH, aH + AHALF, WH_W, WL_W, acc, wm, wn, lane);

        const int t0 = t * 64;
        const int lg = lane >> 2, lt = lane & 3;
#pragma unroll
        for (int nf = 0; nf < 4; nf++) {
            int row = wm + lg;
            int col = wn + nf * 8 + lt * 2;
            int g0 = t0 + row, g1 = g0 + 8;
            float b0 = __ldg(&bias[col]), b1v = __ldg(&bias[col + 1]);
            float v0 = fmaxf(acc[nf][0] + b0, 0.f);
            float v1 = fmaxf(acc[nf][1] + b1v, 0.f);
            float v2 = fmaxf(acc[nf][2] + b0, 0.f);
            float v3 = fmaxf(acc[nf][3] + b1v, 0.f);
            int wi = col >> 1;
            if (g0 < nrows) {
                ((uint*)obh)[(size_t)g0 * 64 + wi] = phi(v0, v1);
                ((uint*)obl)[(size_t)g0 * 64 + wi] = plo(v0, v1);
            }
            if (g1 < nrows) {
                ((uint*)obh)[(size_t)g1 * 64 + wi] = phi(v2, v3);
                ((uint*)obl)[(size_t)g1 * 64 + wi] = plo(v2, v3);
            }
        }
        p ^= 1;
    }
}

// ---------------- dual GEMM, shared A: out1 = A@W1, out2 = A@W2 -> fp16 (fused core) ----------------
__global__ __launch_bounds__(512, 1)
void gk_dual(const u16* __restrict__ Aph, const u16* __restrict__ Apl,
             const u16* __restrict__ W1h_, const u16* __restrict__ W1l_,
             const u16* __restrict__ W2h_, const u16* __restrict__ W2l_,
             u16* __restrict__ out1, u16* __restrict__ out2,
             int nrows, int ntiles)
{
    extern __shared__ uint sm[];
    const int tid = threadIdx.x;
    const int lane = tid & 31, w = tid >> 5;
    const int wm = (w & 3) * 16, wn = (w >> 2) * 32;
    const uint sb = smem_u32(sm);

    load_weights<8>(sm, D_W1H, D_W1L, W1h_, W1l_, tid);
    load_weights<8>(sm, D_W2H, D_W2L, W2h_, W2l_, tid);

    const int r8 = tid >> 3, c8 = tid & 7;
    auto fill_async = [&](int t, int p) {
        int gr = t * 64 + r8;
        int rr = (gr < nrows) ? gr : 0;
        const char* shp = (const char*)(Aph + (size_t)rr * H) + c8 * 16;
        const char* slp = (const char*)(Apl + (size_t)rr * H) + c8 * 16;
        uint dh = sb + (D_ABASE + p * D_ABUF + r8 * WROW + c8 * 4) * 4;
        uint dl = dh + D_AHALF * 4;
        cpa16(dh, shp);        cpa16(dh + 128, shp + 128);
        cpa16(dl, slp);        cpa16(dl + 128, slp + 128);
        CPA_COMMIT();
    };

    int p = 0;
    fill_async(blockIdx.x < ntiles ? blockIdx.x : 0, 0);

    for (int t = blockIdx.x; t < ntiles; t += gridDim.x) {
        __syncthreads();
        int tn = t + gridDim.x;
        fill_async(tn < ntiles ? tn : t, p ^ 1);
        CPA_WAIT(1);
        __syncthreads();

        int aH = D_ABASE + p * D_ABUF;
        float acc1[4][4], acc2[4][4];
#pragma unroll
        for (int nf = 0; nf < 4; nf++)
#pragma unroll
            for (int q = 0; q < 4; q++) { acc1[nf][q] = 0.f; acc2[nf][q] = 0.f; }
        gemm_dual_lm<8>(sb, aH, aH + D_AHALF, D_W1H, D_W1L, D_W2H, D_W2L,
                        acc1, acc2, wm, wn, lane);

        const int t0 = t * 64;
        const int lg = lane >> 2, lt = lane & 3;
#pragma unroll
        for (int nf = 0; nf < 4; nf++) {
            int row = wm + lg;
            int col = wn + nf * 8 + lt * 2;
            int g0 = t0 + row, g1 = g0 + 8;
            int wi = col >> 1;
            if (g0 < nrows) {
                ((uint*)out1)[(size_t)g0 * 64 + wi] = h2u(acc1[nf][0], acc1[nf][1]);
                ((uint*)out2)[(size_t)g0 * 64 + wi] = h2u(acc2[nf][0], acc2[nf][1]);
            }
            if (g1 < nrows) {
                ((uint*)out1)[(size_t)g1 * 64 + wi] = h2u(acc1[nf][2], acc1[nf][3]);
                ((uint*)out2)[(size_t)g1 * 64 + wi] = h2u(acc2[nf][2], acc2[nf][3]);
            }
        }
        p ^= 1;
    }
}

// ---------------- update fused: hid = ReLU(e@U1T + (Hagg*inv_deg)@WC + bias) -> bf16 ----------------
// deg==0 rows: A2 = ReLU(P+Q+mb1) inline; consumes Hagg and zeroes it for next layer
__global__ __launch_bounds__(512, 1)
void gk_upd(const u16* __restrict__ Aph, const u16* __restrict__ Apl,
            float* __restrict__ Hagg,
            const u16* __restrict__ Pq, const u16* __restrict__ Qq,
            const float* __restrict__ mb1,
            const u16* __restrict__ W1h_, const u16* __restrict__ W1l_,
            const u16* __restrict__ W2h_, const u16* __restrict__ W2l_,
            const float* __restrict__ bias, const int* __restrict__ deg,
            u16* __restrict__ obh, u16* __restrict__ obl,
            int nrows, int ntiles)
{
    extern __shared__ uint sm[];
    const int tid = threadIdx.x;
    const int lane = tid & 31, w = tid >> 5;
    const int wm = (w & 3) * 16, wn = (w >> 2) * 32;
    const uint sb = smem_u32(sm);

    load_weights<8>(sm, D_W1H, D_W1L, W1h_, W1l_, tid);
    load_weights<8>(sm, D_W2H, D_W2L, W2h_, W2l_, tid);

    const int r8 = tid >> 3, c8 = tid & 7;

    for (int t = blockIdx.x; t < ntiles; t += gridDim.x) {
        const int t0 = t * 64;
        int gr = t0 + r8;
        int rr = (gr < nrows) ? gr : 0;
        __syncthreads();
        {   // A1: e via cp.async
            const char* shp = (const char*)(Aph + (size_t)rr * H) + c8 * 16;
            const char* slp = (const char*)(Apl + (size_t)rr * H) + c8 * 16;
            uint dh = sb + (D_ABASE + r8 * WROW + c8 * 4) * 4;
            uint dl = dh + D_AHALF * 4;
            cpa16(dh, shp);        cpa16(dh + 128, shp + 128);
            cpa16(dl, slp);        cpa16(dl + 128, slp + 128);
            CPA_COMMIT();
        }
        {   // A2: Hagg * inv_deg  (or iso: ReLU(P+Q+mb1)); zero Hagg after reading
            int d = deg[rr];
            int base = D_ABASE + D_ABUF + r8 * WROW + c8 * 8;
            float vals[16];
            if (d == 0) {
                const uint4* pp = (const uint4*)(Pq + (size_t)rr * H + c8 * 16);
                const uint4* qq = (const uint4*)(Qq + (size_t)rr * H + c8 * 16);
#pragma unroll
                for (int q = 0; q < 2; q++) {
                    uint4 xv = pp[q], yv = qq[q];
                    uint xu[4] = {xv.x, xv.y, xv.z, xv.w};
                    uint yu[4] = {yv.x, yv.y, yv.z, yv.w};
#pragma unroll
                    for (int k = 0; k < 4; k++) {
                        float2 fx = u2f(xu[k]), fy = u2f(yu[k]);
                        int c = c8 * 16 + q * 8 + k * 2;
                        vals[q * 8 + k * 2]     = fmaxf(fx.x + fy.x + __ldg(&mb1[c]),     0.f);
                        vals[q * 8 + k * 2 + 1] = fmaxf(fx.y + fy.y + __ldg(&mb1[c + 1]), 0.f);
                    }
                }
            } else {
                float sc = 1.f / (d > 1 ? (float)d : 1.f);
                float4* s = (float4*)(Hagg + (size_t)rr * H) + c8 * 4;
#pragma unroll
                for (int q = 0; q < 4; q++) {
                    float4 v = s[q];
                    vals[4*q] = v.x*sc; vals[4*q+1] = v.y*sc; vals[4*q+2] = v.z*sc; vals[4*q+3] = v.w*sc;
                }
                if (gr < nrows) {   // owner tile only: recycle to zero for next layer's msum
                    float4 z = make_float4(0.f, 0.f, 0.f, 0.f);
#pragma unroll
                    for (int q = 0; q < 4; q++) s[q] = z;
                }
            }
#pragma unroll
            for (int q = 0; q < 4; q++) {
                *(uint2*)(sm + base + 2 * q) =
                    make_uint2(phi(vals[4*q], vals[4*q+1]), phi(vals[4*q+2], vals[4*q+3]));
                *(uint2*)(sm + base + D_AHALF + 2 * q) =
                    make_uint2(plo(vals[4*q], vals[4*q+1]), plo(vals[4*q+2], vals[4*q+3]));
            }
        }
        CPA_WAIT(0);
        __syncthreads();

        float acc[4][4];
#pragma unroll
        for (int nf = 0; nf < 4; nf++)
#pragma unroll
            for (int q = 0; q < 4; q++) acc[nf][q] = 0.f;
        gemm_core_lm<8>(sb, D_ABASE, D_ABASE + D_AHALF, D_W1H, D_W1L, acc, wm, wn, lane);
        gemm_core_lm<8>(sb, D_ABASE + D_ABUF, D_ABASE + D_ABUF + D_AHALF, D_W2H, D_W2L, acc, wm, wn, lane);

        const int lg = lane >> 2, lt = lane & 3;
#pragma unroll
        for (int nf = 0; nf < 4; nf++) {
            int row = wm + lg;
            int col = wn + nf * 8 + lt * 2;
            int g0 = t0 + row, g1 = g0 + 8;
            float b0 = __ldg(&bias[col]), b1v = __ldg(&bias[col + 1]);
            float v0 = fmaxf(acc[nf][0] + b0, 0.f);
            float v1 = fmaxf(acc[nf][1] + b1v, 0.f);
            float v2 = fmaxf(acc[nf][2] + b0, 0.f);
            float v3 = fmaxf(acc[nf][3] + b1v, 0.f);
            int wi = col >> 1;
            if (g0 < nrows) {
                ((uint*)obh)[(size_t)g0 * 64 + wi] = phi(v0, v1);
                ((uint*)obl)[(size_t)g0 * 64 + wi] = plo(v0, v1);
            }
            if (g1 < nrows) {
                ((uint*)obh)[(size_t)g1 * 64 + wi] = phi(v2, v3);
                ((uint*)obl)[(size_t)g1 * 64 + wi] = plo(v2, v3);
            }
        }
    }
}

// ---------------- pairsum GEMM + predictor epilogue (X,Y fp16) ----------------
__global__ __launch_bounds__(512, 1)
void gk_pair(const u16* __restrict__ X, const u16* __restrict__ Y,
             const int* __restrict__ idx0, const int* __restrict__ idx1,
             const u16* __restrict__ Wth, const u16* __restrict__ Wtl,
             const float* __restrict__ b1, const float* __restrict__ b2,
             const float* __restrict__ W3, const float* __restrict__ b3,
             float* __restrict__ pout,
             int nrows, int ntiles, int logit_off)
{
    extern __shared__ uint sm[];
    float* sp = (float*)(sm + CTRL_W);

    const int tid = threadIdx.x;
    const int lane = tid & 31, w = tid >> 5;
    const int wm = (w & 3) * 16, wn = (w >> 2) * 32;
    const uint sb = smem_u32(sm);

    load_weights<8>(sm, WH_W, WL_W, Wth, Wtl, tid);

    const int r8 = tid >> 3, c8 = tid & 7;

    for (int t = blockIdx.x; t < ntiles; t += gridDim.x) {
        const int t0 = t * 64;
        {
            int gr = t0 + r8;
            int rr = (gr < nrows) ? gr : 0;
            int i0 = __ldg(&idx0[rr]);
            int i1 = __ldg(&idx1[rr]);
            int ch = c8 * 16;
            const uint4* xp = (const uint4*)(X + (size_t)i0 * H + ch);
            const uint4* yp = (const uint4*)(Y + (size_t)i1 * H + ch);
            int base = ABASE + r8 * WROW + c8 * 8;
            __syncthreads();
#pragma unroll
            for (int q = 0; q < 2; q++) {
                uint4 xv = xp[q], yv = yp[q];
                uint xu[4] = {xv.x, xv.y, xv.z, xv.w};
                uint yu[4] = {yv.x, yv.y, yv.z, yv.w};
                float v[8];
#pragma unroll
                for (int k = 0; k < 4; k++) {
                    float2 fx = u2f(xu[k]), fy = u2f(yu[k]);
                    int c = ch + q * 8 + k * 2;
                    v[2*k]     = fmaxf(fx.x + fy.x + __ldg(&b1[c]),     0.f);
                    v[2*k + 1] = fmaxf(fx.y + fy.y + __ldg(&b1[c + 1]), 0.f);
                }
#pragma unroll
                for (int k = 0; k < 4; k++) {
                    sm[base + q * 4 + k]         = phi(v[2*k], v[2*k+1]);
                    sm[base + AHALF + q * 4 + k] = plo(v[2*k], v[2*k+1]);
                }
            }
        }
        __syncthreads();

        float acc[4][4];
#pragma unroll
        for (int nf = 0; nf < 4; nf++)
#pragma unroll
            for (int q = 0; q < 4; q++) acc[nf][q] = 0.f;
        gemm_core_lm<8>(sb, ABASE, ABASE + AHALF, WH_W, WL_W, acc, wm, wn, lane);

        const int lg = lane >> 2, lt = lane & 3;
        float p0 = 0.f, p1 = 0.f;
#pragma unroll
        for (int nf = 0; nf < 4; nf++) {
            int col = wn + nf * 8 + lt * 2;
            float b0 = __ldg(&b2[col]), b1v = __ldg(&b2[col + 1]);
            float w30 = __ldg(&W3[col]), w31 = __ldg(&W3[col + 1]);
            p0 += fmaxf(acc[nf][0] + b0, 0.f) * w30
                + fmaxf(acc[nf][1] + b1v, 0.f) * w31;
            p1 += fmaxf(acc[nf][2] + b0, 0.f) * w30
                + fmaxf(acc[nf][3] + b1v, 0.f) * w31;
        }
        p0 += __shfl_xor_sync(0xFFFFFFFFu, p0, 1);
        p0 += __shfl_xor_sync(0xFFFFFFFFu, p0, 2);
        p1 += __shfl_xor_sync(0xFFFFFFFFu, p1, 1);
        p1 += __shfl_xor_sync(0xFFFFFFFFu, p1, 2);
        if (lt == 0) {
            sp[wm + lg +     64 * (wn >> 5)] = p0;
            sp[wm + lg + 8 + 64 * (wn >> 5)] = p1;
        }
        __syncthreads();
        if (tid < 64) {
            int r = t0 + tid;
            if (r < nrows) {
                float s = sp[tid] + sp[tid + 64] + sp[tid + 128] + sp[tid + 192] + __ldg(&b3[0]);
                pout[r] = 1.f / (1.f + expf(-s));
                if (logit_off > 0) pout[logit_off + r] = s;
            }
        }
    }
}

// ---------------- host ----------------
extern "C" void kernel_launch(void* const* d_in, const int* in_sizes, int n_in,
                              void* d_out, int out_size) {
    const float* feat    = (const float*)d_in[0];
    const int*   adj_dst = (const int*)  d_in[1];
    const int*   adj_src = (const int*)  d_in[2];
    const int*   cand_i  = (const int*)  d_in[3];
    const int*   cand_j  = (const int*)  d_in[4];
    const float* enc_W1 = (const float*)d_in[5];
    const float* enc_b1 = (const float*)d_in[6];
    const float* enc_W2 = (const float*)d_in[7];
    const float* enc_b2 = (const float*)d_in[8];
    const float* msg_W1 = (const float*)d_in[9];
    const float* msg_b1 = (const float*)d_in[10];
    const float* msg_W2 = (const float*)d_in[11];
    const float* msg_b2 = (const float*)d_in[12];
    const float* upd_W1 = (const float*)d_in[13];
    const float* upd_b1 = (const float*)d_in[14];
    const float* upd_W2 = (const float*)d_in[15];
    const float* upd_b2 = (const float*)d_in[16];
    const float* pred_W1 = (const float*)d_in[17];
    const float* pred_b1 = (const float*)d_in[18];
    const float* pred_W2 = (const float*)d_in[19];
    const float* pred_b2 = (const float*)d_in[20];
    const float* pred_W3 = (const float*)d_in[21];
    const float* pred_b3 = (const float*)d_in[22];

    int NE = in_sizes[0] / 64;
    int NA = in_sizes[1];
    int NC = in_sizes[3];
    if (NE > NE_MAX) NE = NE_MAX;

    float *Hagg, *bc;
    int* deg;
    u16 *eh, *el, *e2h, *e2l, *hh, *hl, *wh, *wl, *Pq, *Qq;
    cudaGetSymbolAddress((void**)&Pq,   g_Pq);
    cudaGetSymbolAddress((void**)&Qq,   g_Qq);
    cudaGetSymbolAddress((void**)&Hagg, g_agg);
    cudaGetSymbolAddress((void**)&deg,  g_deg);
    cudaGetSymbolAddress((void**)&bc,   g_bc);
    cudaGetSymbolAddress((void**)&eh,   g_eh);
    cudaGetSymbolAddress((void**)&el,   g_el);
    cudaGetSymbolAddress((void**)&e2h,  g_e2h);
    cudaGetSymbolAddress((void**)&e2l,  g_e2l);
    cudaGetSymbolAddress((void**)&hh,   g_hh);
    cudaGetSymbolAddress((void**)&hl,   g_hl);
    cudaGetSymbolAddress((void**)&wh,   g_wh);
    cudaGetSymbolAddress((void**)&wl,   g_wl);

    cudaFuncSetAttribute(gk_enc,   cudaFuncAttributeMaxDynamicSharedMemorySize, D_SMEM_BYTES);
    cudaFuncSetAttribute(gk_plain, cudaFuncAttributeMaxDynamicSharedMemorySize, SMEM_BYTES);
    cudaFuncSetAttribute(gk_dual,  cudaFuncAttributeMaxDynamicSharedMemorySize, D_SMEM_BYTES);
    cudaFuncSetAttribute(gk_upd,   cudaFuncAttributeMaxDynamicSharedMemorySize, D_SMEM_BYTES);
    cudaFuncSetAttribute(gk_pair,  cudaFuncAttributeMaxDynamicSharedMemorySize, SMEM_BYTES);

    cudaMemsetAsync(deg, 0, (size_t)NE * sizeof(int));
    cudaMemsetAsync(Hagg, 0, (size_t)NE * H * sizeof(float));   // once; gk_upd recycles
    deg_kernel<<<(NA + 255) / 256, 256>>>(adj_dst, NA, deg);

    // ---- weight prep ----
    PJobs pj;
    int cursor = 0, nj = 0;
    auto addjob = [&](const float* W, int ro, int K, int off) {
        pj.W[nj] = W; pj.rowoff[nj] = ro; pj.K[nj] = K; pj.off[nj] = off;
        pj.start[nj] = cursor; cursor += 128 * K; nj++;
    };
    addjob(enc_W1, 0, 64, OFF_ENC1);
    addjob(enc_W2, 0, 128, OFF_ENC2);
    for (int l = 0; l < 3; l++) {
        const float* mW1 = msg_W1 + (size_t)l * 2 * H * H;
        const float* uW1 = upd_W1 + (size_t)l * 2 * H * H;
        const float* uW2 = upd_W2 + (size_t)l * H * H;
        addjob(mW1, 0,   128, OFF_W1T(l));
        addjob(mW1, 128, 128, OFF_W1B(l));
        addjob(uW1, 0,   128, OFF_U1T(l));
        addjob(uW2, 0,   128, OFF_UW2(l));
    }
    addjob(pred_W1, 0,   128, OFF_P1T);
    addjob(pred_W1, 128, 128, OFF_P1B);
    addjob(pred_W2, 0,   128, OFF_P2);
    pj.njobs = nj; pj.total = cursor;
    prep_all<<<(cursor + 255) / 256, 256>>>(pj);
    compprep<<<195, 256>>>(upd_W1, msg_W2, msg_b2, upd_b1);

    int gNE = (NE + 63) / 64;
    int gNC = (NC + 63) / 64;
    int gE = gNE < 148 ? gNE : 148;
    int gC = gNC < 148 ? gNC : 148;

    // fused encoder
    gk_enc<<<gE, 512, D_SMEM_BYTES>>>(
        feat, wh + OFF_ENC1, wl + OFF_ENC1, wh + OFF_ENC2, wl + OFF_ENC2,
        enc_b1, enc_b2, eh, el, NE, gNE);

    u16 *ch = eh, *cl = el, *nh = e2h, *nl = e2l;
    for (int l = 0; l < 3; l++) {
        const float* mb1 = msg_b1 + (size_t)l * H;
        const float* ub2 = upd_b2 + (size_t)l * H;

        gk_dual<<<gE, 512, D_SMEM_BYTES>>>(
            ch, cl, wh + OFF_W1T(l), wl + OFF_W1T(l),
            wh + OFF_W1B(l), wl + OFF_W1B(l), Pq, Qq, NE, gNE);

        msum<<<(NA + 127) / 128, 256>>>(Pq, Qq, mb1, adj_dst, adj_src, Hagg, NA);

        gk_upd<<<gE, 512, D_SMEM_BYTES>>>(
            ch, cl, Hagg, Pq, Qq, mb1,
            wh + OFF_U1T(l), wl + OFF_U1T(l), wh + OFF_WC(l), wl + OFF_WC(l),
            bc + l * H, deg, hh, hl, NE, gNE);

        gk_plain<<<gE, 512, SMEM_BYTES>>>(
            hh, hl, wh + OFF_UW2(l), wl + OFF_UW2(l),
            ub2, nh, nl, NE, gNE);

        u16* t1 = ch; ch = nh; nh = t1;
        u16* t2 = cl; cl = nl; nl = t2;
    }

    gk_dual<<<gE, 512, D_SMEM_BYTES>>>(
        ch, cl, wh + OFF_P1T, wl + OFF_P1T,
        wh + OFF_P1B, wl + OFF_P1B, Pq, Qq, NE, gNE);
    int logit_off = (out_size >= 2 * NC) ? NC : -1;
    gk_pair<<<gC, 512, SMEM_BYTES>>>(
        Pq, Qq, cand_i, cand_j, wh + OFF_P2, wl + OFF_P2,
        pred_b1, pred_b2, pred_W3, pred_b3,
        (float*)d_out, NC, gNC, logit_off);
}

// round 15
// speedup vs baseline: 1.0051x; 1.0051x over previous
#include <cuda_runtime.h>
#include <cuda_bf16.h>
#include <cuda_fp16.h>
#include <stdint.h>
#include <math.h>

#define H 128
#define NE_MAX 50000

typedef unsigned int uint;
typedef unsigned short u16;

// ---------------- device scratch (allocation-free rule) ----------------
__device__ u16   g_eh [NE_MAX * H];
__device__ u16   g_el [NE_MAX * H];
__device__ u16   g_e2h[NE_MAX * H];
__device__ u16   g_e2l[NE_MAX * H];
__device__ u16   g_hh [NE_MAX * H];
__device__ u16   g_hl [NE_MAX * H];
__device__ u16   g_Pq [NE_MAX * H];      // fp16 P
__device__ u16   g_Qq [NE_MAX * H];      // fp16 Q
__device__ float g_agg[NE_MAX * H];
__device__ int   g_deg[NE_MAX];
__device__ float g_bc [3 * H];
#define WSCRATCH 368640
__device__ u16 g_wh[WSCRATCH];
__device__ u16 g_wl[WSCRATCH];

// transposed/split weight offsets (elements)
#define OFF_ENC1 0
#define OFF_ENC2 8192
#define OFF_L(l)   (24576 + (l) * 98304)
#define OFF_W1T(l) (OFF_L(l))
#define OFF_W1B(l) (OFF_L(l) + 16384)
#define OFF_WC(l)  (OFF_L(l) + 32768)
#define OFF_U1T(l) (OFF_L(l) + 49152)
#define OFF_UW2(l) (OFF_L(l) + 81920)
#define OFF_P1T 319488
#define OFF_P1B 335872
#define OFF_P2  352256

// ---- single-GEMM smem layout ----
#define WROW 68
#define WH_W 0
#define WL_W 8704
#define ABASE 17408
#define ABUF  8704
#define AHALF 4352
#define CTRL_W 34816
#define SMEM_WORDS 35104
#define SMEM_BYTES (SMEM_WORDS * 4)

// ---- dual-GEMM smem layout ----
#define D_W1H 0
#define D_W1L 8704
#define D_W2H 17408
#define D_W2L 26112
#define D_ABASE 34816
#define D_ABUF  8704
#define D_AHALF 4352
#define D_SMEM_WORDS 52224
#define D_SMEM_BYTES (D_SMEM_WORDS * 4)

// ---------------- helpers ----------------
__device__ __forceinline__ uint phi(float a, float b) {
    return (uint)__bfloat16_as_ushort(__float2bfloat16_rn(a))
         | ((uint)__bfloat16_as_ushort(__float2bfloat16_rn(b)) << 16);
}
__device__ __forceinline__ uint plo(float a, float b) {
    float ah = __bfloat162float(__float2bfloat16_rn(a));
    float bh = __bfloat162float(__float2bfloat16_rn(b));
    return phi(a - ah, b - bh);
}
__device__ __forceinline__ uint h2u(float a, float b) {
    __half2 h = __floats2half2_rn(a, b);
    return *(uint*)&h;
}
__device__ __forceinline__ float2 u2f(uint u) {
    return __half22float2(*(const __half2*)&u);
}
__device__ __forceinline__ uint smem_u32(const void* p) {
    uint a;
    asm("{ .reg .u64 t; cvta.to.shared.u64 t, %1; cvt.u32.u64 %0, t; }" : "=r"(a) : "l"(p));
    return a;
}
__device__ __forceinline__ void cpa16(uint dst, const void* src) {
    asm volatile("cp.async.cg.shared.global [%0], [%1], 16;" :: "r"(dst), "l"(src));
}
#define CPA_COMMIT() asm volatile("cp.async.commit_group;" ::: "memory")
#define CPA_WAIT(n)  asm volatile("cp.async.wait_group %0;" :: "n"(n) : "memory")

__device__ __forceinline__ void mma_bf(float* c, uint a0, uint a1, uint a2, uint a3,
                                       uint b0, uint b1) {
    asm volatile(
        "mma.sync.aligned.m16n8k16.row.col.f32.bf16.bf16.f32 "
        "{%0,%1,%2,%3},{%4,%5,%6,%7},{%8,%9},{%0,%1,%2,%3};"
        : "+f"(c[0]), "+f"(c[1]), "+f"(c[2]), "+f"(c[3])
        : "r"(a0), "r"(a1), "r"(a2), "r"(a3), "r"(b0), "r"(b1));
}
__device__ __forceinline__ void ldsm4(uint& r0, uint& r1, uint& r2, uint& r3, uint addr) {
    asm volatile("ldmatrix.sync.aligned.m8n8.x4.shared.b16 {%0,%1,%2,%3}, [%4];"
        : "=r"(r0), "=r"(r1), "=r"(r2), "=r"(r3) : "r"(addr));
}

// warp tile 16x32 via ldmatrix; 16 warps = 4(M) x 4(N); M-tile 64, N 128
template <int NK>
__device__ __forceinline__ void gemm_core_lm(uint sb, int aH, int aL, int wH, int wL,
                                             float acc[4][4], int wm, int wn, int lane) {
    const int l7 = lane & 7, lm = lane >> 3;
    const int radd = (lm & 1) * 8;
    const int koff = (lm >> 1) * 4;
    uint aBh  = sb + ((uint)(aH + (wm + l7 + radd) * WROW + koff) << 2);
    uint aBl  = sb + ((uint)(aL + (wm + l7 + radd) * WROW + koff) << 2);
    uint bBh0 = sb + ((uint)(wH + (wn + l7 + radd) * WROW + koff) << 2);
    uint bBl0 = sb + ((uint)(wL + (wn + l7 + radd) * WROW + koff) << 2);
    uint bBh1 = bBh0 + 16 * WROW * 4;
    uint bBl1 = bBl0 + 16 * WROW * 4;
#pragma unroll
    for (int ks = 0; ks < NK; ks++) {
        uint ko = ks * 32;
        uint ah0, ah1, ah2, ah3, al0, al1, al2, al3;
        ldsm4(ah0, ah1, ah2, ah3, aBh + ko);
        ldsm4(al0, al1, al2, al3, aBl + ko);
        uint p0, p1, p2, p3, q0, q1, q2, q3;
        ldsm4(p0, p1, p2, p3, bBh0 + ko);
        ldsm4(q0, q1, q2, q3, bBh1 + ko);
        uint u0, u1, u2, u3, v0, v1, v2, v3;
        ldsm4(u0, u1, u2, u3, bBl0 + ko);
        ldsm4(v0, v1, v2, v3, bBl1 + ko);
        mma_bf(acc[0], ah0, ah1, ah2, ah3, p0, p2);
        mma_bf(acc[1], ah0, ah1, ah2, ah3, p1, p3);
        mma_bf(acc[2], ah0, ah1, ah2, ah3, q0, q2);
        mma_bf(acc[3], ah0, ah1, ah2, ah3, q1, q3);
        mma_bf(acc[0], ah0, ah1, ah2, ah3, u0, u2);
        mma_bf(acc[1], ah0, ah1, ah2, ah3, u1, u3);
        mma_bf(acc[2], ah0, ah1, ah2, ah3, v0, v2);
        mma_bf(acc[3], ah0, ah1, ah2, ah3, v1, v3);
        mma_bf(acc[0], al0, al1, al2, al3, p0, p2);
        mma_bf(acc[1], al0, al1, al2, al3, p1, p3);
        mma_bf(acc[2], al0, al1, al2, al3, q0, q2);
        mma_bf(acc[3], al0, al1, al2, al3, q1, q3);
    }
}

template <int NK>
__device__ __forceinline__ void load_weights(uint* sm, int dH, int dL,
                                             const u16* Wth, const u16* Wtl, int tid) {
    const int nv = 128 * NK * 2;
    const uint4* sh = (const uint4*)Wth;
    const uint4* sl = (const uint4*)Wtl;
    for (int i = tid; i < nv; i += 512) {
        int n = i / (NK * 2), q = i % (NK * 2);
        *(uint4*)(sm + dH + n * WROW + q * 4) = sh[i];
        *(uint4*)(sm + dL + n * WROW + q * 4) = sl[i];
    }
}

// ---------------- small kernels ----------------
__global__ void deg_kernel(const int* __restrict__ dst, int na, int* __restrict__ deg) {
    int i = blockIdx.x * blockDim.x + threadIdx.x;
    if (i < na) atomicAdd(&deg[dst[i]], 1);
}

struct PJobs {
    const float* W[20];
    int rowoff[20], K[20], off[20], start[20];
    int njobs, total;
};
__global__ void prep_all(PJobs j) {
    int i = blockIdx.x * 256 + threadIdx.x;
    if (i >= j.total) return;
    int a = 0;
    while (a + 1 < j.njobs && i >= j.start[a + 1]) a++;
    int e = i - j.start[a];
    int K = j.K[a];
    int n = e / K, k = e % K;
    float v = j.W[a][(size_t)(j.rowoff[a] + k) * 128 + n];
    __nv_bfloat16 h = __float2bfloat16_rn(v);
    g_wh[j.off[a] + e] = __bfloat16_as_ushort(h);
    g_wl[j.off[a] + e] = __bfloat16_as_ushort(__float2bfloat16_rn(v - __bfloat162float(h)));
}

__global__ void compprep(const float* __restrict__ upd_W1,
                         const float* __restrict__ msg_W2,
                         const float* __restrict__ msg_b2,
                         const float* __restrict__ upd_b1) {
    int b = blockIdx.x;
    if (b < 192) {
        int l = b >> 6;
        int i = (b & 63) * 256 + threadIdx.x;
        int o = i & 127, h = i >> 7;
        const float* W2  = msg_W2 + (size_t)l * 16384;
        const float* U1b = upd_W1 + (size_t)l * 32768 + 16384;
        float s = 0.f;
        for (int a2 = 0; a2 < 128; a2++) s += W2[h * 128 + a2] * U1b[a2 * 128 + o];
        int li = OFF_WC(l) + o * 128 + h;
        __nv_bfloat16 hh = __float2bfloat16_rn(s);
        g_wh[li] = __bfloat16_as_ushort(hh);
        g_wl[li] = __bfloat16_as_ushort(__float2bfloat16_rn(s - __bfloat162float(hh)));
    } else if (b < 195) {
        int l = b - 192;
        int o = threadIdx.x;
        if (o < 128) {
            const float* U1b = upd_W1 + (size_t)l * 32768 + 16384;
            const float* b2  = msg_b2 + (size_t)l * 128;
            float s = upd_b1[l * 128 + o];
            for (int a2 = 0; a2 < 128; a2++) s += b2[a2] * U1b[a2 * 128 + o];
            g_bc[l * 128 + o] = s;
        }
    }
}

// pair hidden aggregation: Hagg[dst] += ReLU(P[dst] + Q[src] + b1)  (P,Q fp16)
__global__ __launch_bounds__(256) void msum(const u16* __restrict__ P,
                                            const u16* __restrict__ Q,
                                            const float* __restrict__ b1,
                                            const int* __restrict__ dst,
                                            const int* __restrict__ src,
                                            float* __restrict__ Hagg, int na) {
    int team = threadIdx.x >> 7, col = threadIdx.x & 127;
    int p0 = blockIdx.x * 128 + team * 64;
    if (p0 >= na) return;
    float bias = __ldg(&b1[col]);
    float sum = 0.f, pv = 0.f;
    int cur = -1;
    for (int base = 0; base < 64; base += 8) {
        int dd[8], ss[8];
#pragma unroll
        for (int j = 0; j < 8; j++) {
            int a = p0 + base + j;
            bool v = a < na;
            dd[j] = v ? __ldg(&dst[a]) : -1;
            ss[j] = v ? __ldg(&src[a]) : 0;
        }
        float qv[8];
#pragma unroll
        for (int j = 0; j < 8; j++)
            qv[j] = __half2float(((const __half*)Q)[(size_t)ss[j] * H + col]);
#pragma unroll
        for (int j = 0; j < 8; j++) {
            if (dd[j] != cur) {
                if (cur >= 0) atomicAdd(&Hagg[(size_t)cur * H + col], sum);
                cur = dd[j];
                sum = 0.f;
                if (cur >= 0)
                    pv = __half2float(((const __half*)P)[(size_t)cur * H + col]) + bias;
            }
            if (dd[j] >= 0) sum += fmaxf(pv + qv[j], 0.f);
        }
    }
    if (cur >= 0) atomicAdd(&Hagg[(size_t)cur * H + col], sum);
}

// ---------------- fused encoder ----------------
__global__ __launch_bounds__(512, 1)
void gk_enc(const float* __restrict__ feat,
            const u16* __restrict__ W1h_, const u16* __restrict__ W1l_,
            const u16* __restrict__ W2h_, const u16* __restrict__ W2l_,
            const float* __restrict__ b1, const float* __restrict__ b2,
            u16* __restrict__ obh, u16* __restrict__ obl,
            int nrows, int ntiles)
{
    extern __shared__ uint sm[];
    const int tid = threadIdx.x;
    const int lane = tid & 31, w = tid >> 5;
    const int wm = (w & 3) * 16, wn = (w >> 2) * 32;
    const uint sb = smem_u32(sm);
    const int HID = D_ABASE + D_ABUF;

    load_weights<4>(sm, D_W1H, D_W1L, W1h_, W1l_, tid);
    load_weights<8>(sm, D_W2H, D_W2L, W2h_, W2l_, tid);

    const int r8 = tid >> 3, c8 = tid & 7;
    const int lg = lane >> 2, lt = lane & 3;

    for (int t = blockIdx.x; t < ntiles; t += gridDim.x) {
        const int t0 = t * 64;
        __syncthreads();
        {
            int gr = t0 + r8;
            int rr = (gr < nrows) ? gr : 0;
            const float4* s = (const float4*)(feat + (size_t)rr * 64) + c8 * 2;
            int base = D_ABASE + r8 * WROW + c8 * 4;
#pragma unroll
            for (int q = 0; q < 2; q++) {
                float4 v = s[q];
                *(uint2*)(sm + base + 2 * q)           = make_uint2(phi(v.x, v.y), phi(v.z, v.w));
                *(uint2*)(sm + base + D_AHALF + 2 * q) = make_uint2(plo(v.x, v.y), plo(v.z, v.w));
            }
        }
        __syncthreads();

        float acc[4][4];
#pragma unroll
        for (int nf = 0; nf < 4; nf++)
#pragma unroll
            for (int q = 0; q < 4; q++) acc[nf][q] = 0.f;
        gemm_core_lm<4>(sb, D_ABASE, D_ABASE + D_AHALF, D_W1H, D_W1L, acc, wm, wn, lane);

#pragma unroll
        for (int nf = 0; nf < 4; nf++) {
            int row = wm + lg;
            int col = wn + nf * 8 + lt * 2;
            float b0 = __ldg(&b1[col]), b1v = __ldg(&b1[col + 1]);
            float v0 = fmaxf(acc[nf][0] + b0, 0.f);
            float v1 = fmaxf(acc[nf][1] + b1v, 0.f);
            float v2 = fmaxf(acc[nf][2] + b0, 0.f);
            float v3 = fmaxf(acc[nf][3] + b1v, 0.f);
            int wi = col >> 1;
            sm[HID + row * WROW + wi]                 = phi(v0, v1);
            sm[HID + D_AHALF + row * WROW + wi]       = plo(v0, v1);
            sm[HID + (row + 8) * WROW + wi]           = phi(v2, v3);
            sm[HID + D_AHALF + (row + 8) * WROW + wi] = plo(v2, v3);
        }
        __syncthreads();

#pragma unroll
        for (int nf = 0; nf < 4; nf++)
#pragma unroll
            for (int q = 0; q < 4; q++) acc[nf][q] = 0.f;
        gemm_core_lm<8>(sb, HID, HID + D_AHALF, D_W2H, D_W2L, acc, wm, wn, lane);

#pragma unroll
        for (int nf = 0; nf < 4; nf++) {
            int row = wm + lg;
            int col = wn + nf * 8 + lt * 2;
            int g0 = t0 + row, g1 = g0 + 8;
            float b0 = __ldg(&b2[col]), b1v = __ldg(&b2[col + 1]);
            float v0 = acc[nf][0] + b0, v1 = acc[nf][1] + b1v;
            float v2 = acc[nf][2] + b0, v3 = acc[nf][3] + b1v;
            int wi = col >> 1;
            if (g0 < nrows) {
                ((uint*)obh)[(size_t)g0 * 64 + wi] = phi(v0, v1);
                ((uint*)obl)[(size_t)g0 * 64 + wi] = plo(v0, v1);
            }
            if (g1 < nrows) {
                ((uint*)obh)[(size_t)g1 * 64 + wi] = phi(v2, v3);
                ((uint*)obl)[(size_t)g1 * 64 + wi] = plo(v2, v3);
            }
        }
    }
}

// ---------------- single GEMM (bf16 in, cp.async double-buffer), bias+ReLU -> bf16 ----------------
__global__ __launch_bounds__(512, 1)
void gk_plain(const u16* __restrict__ Aph, const u16* __restrict__ Apl,
              const u16* __restrict__ Wth, const u16* __restrict__ Wtl,
              const float* __restrict__ bias,
              u16* __restrict__ obh, u16* __restrict__ obl,
              int nrows, int ntiles)
{
    extern __shared__ uint sm[];
    const int tid = threadIdx.x;
    const int lane = tid & 31, w = tid >> 5;
    const int wm = (w & 3) * 16, wn = (w >> 2) * 32;
    const uint sb = smem_u32(sm);

    load_weights<8>(sm, WH_W, WL_W, Wth, Wtl, tid);

    const int r8 = tid >> 3, c8 = tid & 7;

    auto fill_async = [&](int t, int p) {
        int gr = t * 64 + r8;
        int rr = (gr < nrows) ? gr : 0;
        const char* shp = (const char*)(Aph + (size_t)rr * H) + c8 * 16;
        const char* slp = (const char*)(Apl + (size_t)rr * H) + c8 * 16;
        uint dh = sb + (ABASE + p * ABUF + r8 * WROW + c8 * 4) * 4;
        uint dl = dh + AHALF * 4;
        cpa16(dh, shp);        cpa16(dh + 128, shp + 128);
        cpa16(dl, slp);        cpa16(dl + 128, slp + 128);
        CPA_COMMIT();
    };

    int p = 0;
    fill_async(blockIdx.x < ntiles ? blockIdx.x : 0, 0);

    for (int t = blockIdx.x; t < ntiles; t += gridDim.x) {
        __syncthreads();
        int tn = t + gridDim.x;
        fill_async(tn < ntiles ? tn : t, p ^ 1);
        CPA_WAIT(1);
        __syncthreads();

        float acc[4][4];
#pragma unroll
        for (int nf = 0; nf < 4; nf++)
#pragma unroll
            for (int q = 0; q < 4; q++) acc[nf][q] = 0.f;
        int aH = ABASE + p * ABUF;
        gemm_core_lm<8>(sb, aH, aH + AHALF, WH_W, WL_W, acc, wm, wn, lane);

        const int t0 = t * 64;
        const int lg = lane >> 2, lt = lane & 3;
#pragma unroll
        for (int nf = 0; nf < 4; nf++) {
            int row = wm + lg;
            int col = wn + nf * 8 + lt * 2;
            int g0 = t0 + row, g1 = g0 + 8;
            float b0 = __ldg(&bias[col]), b1v = __ldg(&bias[col + 1]);
            float v0 = fmaxf(acc[nf][0] + b0, 0.f);
            float v1 = fmaxf(acc[nf][1] + b1v, 0.f);
            float v2 = fmaxf(acc[nf][2] + b0, 0.f);
            float v3 = fmaxf(acc[nf][3] + b1v, 0.f);
            int wi = col >> 1;
            if (g0 < nrows) {
                ((uint*)obh)[(size_t)g0 * 64 + wi] = phi(v0, v1);
                ((uint*)obl)[(size_t)g0 * 64 + wi] = plo(v0, v1);
            }
            if (g1 < nrows) {
                ((uint*)obh)[(size_t)g1 * 64 + wi] = phi(v2, v3);
                ((uint*)obl)[(size_t)g1 * 64 + wi] = plo(v2, v3);
            }
        }
        p ^= 1;
    }
}

// ---------------- dual GEMM, shared A: out1 = A@W1, out2 = A@W2 -> fp16 ----------------
__global__ __launch_bounds__(512, 1)
void gk_dual(const u16* __restrict__ Aph, const u16* __restrict__ Apl,
             const u16* __restrict__ W1h_, const u16* __restrict__ W1l_,
             const u16* __restrict__ W2h_, const u16* __restrict__ W2l_,
             u16* __restrict__ out1, u16* __restrict__ out2,
             int nrows, int ntiles)
{
    extern __shared__ uint sm[];
    const int tid = threadIdx.x;
    const int lane = tid & 31, w = tid >> 5;
    const int wm = (w & 3) * 16, wn = (w >> 2) * 32;
    const uint sb = smem_u32(sm);

    load_weights<8>(sm, D_W1H, D_W1L, W1h_, W1l_, tid);
    load_weights<8>(sm, D_W2H, D_W2L, W2h_, W2l_, tid);

    const int r8 = tid >> 3, c8 = tid & 7;
    auto fill_async = [&](int t, int p) {
        int gr = t * 64 + r8;
        int rr = (gr < nrows) ? gr : 0;
        const char* shp = (const char*)(Aph + (size_t)rr * H) + c8 * 16;
        const char* slp = (const char*)(Apl + (size_t)rr * H) + c8 * 16;
        uint dh = sb + (D_ABASE + p * D_ABUF + r8 * WROW + c8 * 4) * 4;
        uint dl = dh + D_AHALF * 4;
        cpa16(dh, shp);        cpa16(dh + 128, shp + 128);
        cpa16(dl, slp);        cpa16(dl + 128, slp + 128);
        CPA_COMMIT();
    };

    int p = 0;
    fill_async(blockIdx.x < ntiles ? blockIdx.x : 0, 0);

    for (int t = blockIdx.x; t < ntiles; t += gridDim.x) {
        __syncthreads();
        int tn = t + gridDim.x;
        fill_async(tn < ntiles ? tn : t, p ^ 1);
        CPA_WAIT(1);
        __syncthreads();

        int aH = D_ABASE + p * D_ABUF;
        float acc1[4][4], acc2[4][4];
#pragma unroll
        for (int nf = 0; nf < 4; nf++)
#pragma unroll
            for (int q = 0; q < 4; q++) { acc1[nf][q] = 0.f; acc2[nf][q] = 0.f; }
        gemm_core_lm<8>(sb, aH, aH + D_AHALF, D_W1H, D_W1L, acc1, wm, wn, lane);
        gemm_core_lm<8>(sb, aH, aH + D_AHALF, D_W2H, D_W2L, acc2, wm, wn, lane);

        const int t0 = t * 64;
        const int lg = lane >> 2, lt = lane & 3;
#pragma unroll
        for (int nf = 0; nf < 4; nf++) {
            int row = wm + lg;
            int col = wn + nf * 8 + lt * 2;
            int g0 = t0 + row, g1 = g0 + 8;
            int wi = col >> 1;
            if (g0 < nrows) {
                ((uint*)out1)[(size_t)g0 * 64 + wi] = h2u(acc1[nf][0], acc1[nf][1]);
                ((uint*)out2)[(size_t)g0 * 64 + wi] = h2u(acc2[nf][0], acc2[nf][1]);
            }
            if (g1 < nrows) {
                ((uint*)out1)[(size_t)g1 * 64 + wi] = h2u(acc1[nf][2], acc1[nf][3]);
                ((uint*)out2)[(size_t)g1 * 64 + wi] = h2u(acc2[nf][2], acc2[nf][3]);
            }
        }
        p ^= 1;
    }
}

// ---------------- update fused: hid = ReLU(e@U1T + (Hagg*inv_deg)@WC + bias) -> bf16 ----------------
// deg==0 rows: A2 = ReLU(P+Q+mb1) inline; consumes Hagg and zeroes it for next layer
__global__ __launch_bounds__(512, 1)
void gk_upd(const u16* __restrict__ Aph, const u16* __restrict__ Apl,
            float* __restrict__ Hagg,
            const u16* __restrict__ Pq, const u16* __restrict__ Qq,
            const float* __restrict__ mb1,
            const u16* __restrict__ W1h_, const u16* __restrict__ W1l_,
            const u16* __restrict__ W2h_, const u16* __restrict__ W2l_,
            const float* __restrict__ bias, const int* __restrict__ deg,
            u16* __restrict__ obh, u16* __restrict__ obl,
            int nrows, int ntiles)
{
    extern __shared__ uint sm[];
    const int tid = threadIdx.x;
    const int lane = tid & 31, w = tid >> 5;
    const int wm = (w & 3) * 16, wn = (w >> 2) * 32;
    const uint sb = smem_u32(sm);

    load_weights<8>(sm, D_W1H, D_W1L, W1h_, W1l_, tid);
    load_weights<8>(sm, D_W2H, D_W2L, W2h_, W2l_, tid);

    const int r8 = tid >> 3, c8 = tid & 7;

    for (int t = blockIdx.x; t < ntiles; t += gridDim.x) {
        const int t0 = t * 64;
        int gr = t0 + r8;
        int rr = (gr < nrows) ? gr : 0;
        __syncthreads();
        {   // A1: e via cp.async
            const char* shp = (const char*)(Aph + (size_t)rr * H) + c8 * 16;
            const char* slp = (const char*)(Apl + (size_t)rr * H) + c8 * 16;
            uint dh = sb + (D_ABASE + r8 * WROW + c8 * 4) * 4;
            uint dl = dh + D_AHALF * 4;
            cpa16(dh, shp);        cpa16(dh + 128, shp + 128);
            cpa16(dl, slp);        cpa16(dl + 128, slp + 128);
            CPA_COMMIT();
        }
        {   // A2: Hagg * inv_deg  (or iso: ReLU(P+Q+mb1)); zero Hagg after reading
            int d = deg[rr];
            int base = D_ABASE + D_ABUF + r8 * WROW + c8 * 8;
            float vals[16];
            if (d == 0) {
                const uint4* pp = (const uint4*)(Pq + (size_t)rr * H + c8 * 16);
                const uint4* qq = (const uint4*)(Qq + (size_t)rr * H + c8 * 16);
#pragma unroll
                for (int q = 0; q < 2; q++) {
                    uint4 xv = pp[q], yv = qq[q];
                    uint xu[4] = {xv.x, xv.y, xv.z, xv.w};
                    uint yu[4] = {yv.x, yv.y, yv.z, yv.w};
#pragma unroll
                    for (int k = 0; k < 4; k++) {
                        float2 fx = u2f(xu[k]), fy = u2f(yu[k]);
                        int c = c8 * 16 + q * 8 + k * 2;
                        vals[q * 8 + k * 2]     = fmaxf(fx.x + fy.x + __ldg(&mb1[c]),     0.f);
                        vals[q * 8 + k * 2 + 1] = fmaxf(fx.y + fy.y + __ldg(&mb1[c + 1]), 0.f);
                    }
                }
            } else {
                float sc = 1.f / (d > 1 ? (float)d : 1.f);
                float4* s = (float4*)(Hagg + (size_t)rr * H) + c8 * 4;
#pragma unroll
                for (int q = 0; q < 4; q++) {
                    float4 v = s[q];
                    vals[4*q] = v.x*sc; vals[4*q+1] = v.y*sc; vals[4*q+2] = v.z*sc; vals[4*q+3] = v.w*sc;
                }
                if (gr < nrows) {   // owner tile only: recycle to zero for next layer's msum
                    float4 z = make_float4(0.f, 0.f, 0.f, 0.f);
#pragma unroll
                    for (int q = 0; q < 4; q++) s[q] = z;
                }
            }
#pragma unroll
            for (int q = 0; q < 4; q++) {
                *(uint2*)(sm + base + 2 * q) =
                    make_uint2(phi(vals[4*q], vals[4*q+1]), phi(vals[4*q+2], vals[4*q+3]));
                *(uint2*)(sm + base + D_AHALF + 2 * q) =
                    make_uint2(plo(vals[4*q], vals[4*q+1]), plo(vals[4*q+2], vals[4*q+3]));
            }
        }
        CPA_WAIT(0);
        __syncthreads();

        float acc[4][4];
#pragma unroll
        for (int nf = 0; nf < 4; nf++)
#pragma unroll
            for (int q = 0; q < 4; q++) acc[nf][q] = 0.f;
        gemm_core_lm<8>(sb, D_ABASE, D_ABASE + D_AHALF, D_W1H, D_W1L, acc, wm, wn, lane);
        gemm_core_lm<8>(sb, D_ABASE + D_ABUF, D_ABASE + D_ABUF + D_AHALF, D_W2H, D_W2L, acc, wm, wn, lane);

        const int lg = lane >> 2, lt = lane & 3;
#pragma unroll
        for (int nf = 0; nf < 4; nf++) {
            int row = wm + lg;
            int col = wn + nf * 8 + lt * 2;
            int g0 = t0 + row, g1 = g0 + 8;
            float b0 = __ldg(&bias[col]), b1v = __ldg(&bias[col + 1]);
            float v0 = fmaxf(acc[nf][0] + b0, 0.f);
            float v1 = fmaxf(acc[nf][1] + b1v, 0.f);
            float v2 = fmaxf(acc[nf][2] + b0, 0.f);
            float v3 = fmaxf(acc[nf][3] + b1v, 0.f);
            int wi = col >> 1;
            if (g0 < nrows) {
                ((uint*)obh)[(size_t)g0 * 64 + wi] = phi(v0, v1);
                ((uint*)obl)[(size_t)g0 * 64 + wi] = plo(v0, v1);
            }
            if (g1 < nrows) {
                ((uint*)obh)[(size_t)g1 * 64 + wi] = phi(v2, v3);
                ((uint*)obl)[(size_t)g1 * 64 + wi] = plo(v2, v3);
            }
        }
    }
}

// ---------------- pairsum GEMM + predictor epilogue (X,Y fp16) ----------------
__global__ __launch_bounds__(512, 1)
void gk_pair(const u16* __restrict__ X, const u16* __restrict__ Y,
             const int* __restrict__ idx0, const int* __restrict__ idx1,
             const u16* __restrict__ Wth, const u16* __restrict__ Wtl,
             const float* __restrict__ b1, const float* __restrict__ b2,
             const float* __restrict__ W3, const float* __restrict__ b3,
             float* __restrict__ pout,
             int nrows, int ntiles, int logit_off)
{
    extern __shared__ uint sm[];
    float* sp = (float*)(sm + CTRL_W);

    const int tid = threadIdx.x;
    const int lane = tid & 31, w = tid >> 5;
    const int wm = (w & 3) * 16, wn = (w >> 2) * 32;
    const uint sb = smem_u32(sm);

    load_weights<8>(sm, WH_W, WL_W, Wth, Wtl, tid);

    const int r8 = tid >> 3, c8 = tid & 7;

    for (int t = blockIdx.x; t < ntiles; t += gridDim.x) {
        const int t0 = t * 64;
        {
            int gr = t0 + r8;
            int rr = (gr < nrows) ? gr : 0;
            int i0 = __ldg(&idx0[rr]);
            int i1 = __ldg(&idx1[rr]);
            int ch = c8 * 16;
            const uint4* xp = (const uint4*)(X + (size_t)i0 * H + ch);
            const uint4* yp = (const uint4*)(Y + (size_t)i1 * H + ch);
            int base = ABASE + r8 * WROW + c8 * 8;
            __syncthreads();
#pragma unroll
            for (int q = 0; q < 2; q++) {
                uint4 xv = xp[q], yv = yp[q];
                uint xu[4] = {xv.x, xv.y, xv.z, xv.w};
                uint yu[4] = {yv.x, yv.y, yv.z, yv.w};
                float v[8];
#pragma unroll
                for (int k = 0; k < 4; k++) {
                    float2 fx = u2f(xu[k]), fy = u2f(yu[k]);
                    int c = ch + q * 8 + k * 2;
                    v[2*k]     = fmaxf(fx.x + fy.x + __ldg(&b1[c]),     0.f);
                    v[2*k + 1] = fmaxf(fx.y + fy.y + __ldg(&b1[c + 1]), 0.f);
                }
#pragma unroll
                for (int k = 0; k < 4; k++) {
                    sm[base + q * 4 + k]         = phi(v[2*k], v[2*k+1]);
                    sm[base + AHALF + q * 4 + k] = plo(v[2*k], v[2*k+1]);
                }
            }
        }
        __syncthreads();

        float acc[4][4];
#pragma unroll
        for (int nf = 0; nf < 4; nf++)
#pragma unroll
            for (int q = 0; q < 4; q++) acc[nf][q] = 0.f;
        gemm_core_lm<8>(sb, ABASE, ABASE + AHALF, WH_W, WL_W, acc, wm, wn, lane);

        const int lg = lane >> 2, lt = lane & 3;
        float p0 = 0.f, p1 = 0.f;
#pragma unroll
        for (int nf = 0; nf < 4; nf++) {
            int col = wn + nf * 8 + lt * 2;
            float b0 = __ldg(&b2[col]), b1v = __ldg(&b2[col + 1]);
            float w30 = __ldg(&W3[col]), w31 = __ldg(&W3[col + 1]);
            p0 += fmaxf(acc[nf][0] + b0, 0.f) * w30
                + fmaxf(acc[nf][1] + b1v, 0.f) * w31;
            p1 += fmaxf(acc[nf][2] + b0, 0.f) * w30
                + fmaxf(acc[nf][3] + b1v, 0.f) * w31;
        }
        p0 += __shfl_xor_sync(0xFFFFFFFFu, p0, 1);
        p0 += __shfl_xor_sync(0xFFFFFFFFu, p0, 2);
        p1 += __shfl_xor_sync(0xFFFFFFFFu, p1, 1);
        p1 += __shfl_xor_sync(0xFFFFFFFFu, p1, 2);
        if (lt == 0) {
            sp[wm + lg +     64 * (wn >> 5)] = p0;
            sp[wm + lg + 8 + 64 * (wn >> 5)] = p1;
        }
        __syncthreads();
        if (tid < 64) {
            int r = t0 + tid;
            if (r < nrows) {
                float s = sp[tid] + sp[tid + 64] + sp[tid + 128] + sp[tid + 192] + __ldg(&b3[0]);
                pout[r] = 1.f / (1.f + expf(-s));
                if (logit_off > 0) pout[logit_off + r] = s;
            }
        }
    }
}

// ---------------- host ----------------
extern "C" void kernel_launch(void* const* d_in, const int* in_sizes, int n_in,
                              void* d_out, int out_size) {
    const float* feat    = (const float*)d_in[0];
    const int*   adj_dst = (const int*)  d_in[1];
    const int*   adj_src = (const int*)  d_in[2];
    const int*   cand_i  = (const int*)  d_in[3];
    const int*   cand_j  = (const int*)  d_in[4];
    const float* enc_W1 = (const float*)d_in[5];
    const float* enc_b1 = (const float*)d_in[6];
    const float* enc_W2 = (const float*)d_in[7];
    const float* enc_b2 = (const float*)d_in[8];
    const float* msg_W1 = (const float*)d_in[9];
    const float* msg_b1 = (const float*)d_in[10];
    const float* msg_W2 = (const float*)d_in[11];
    const float* msg_b2 = (const float*)d_in[12];
    const float* upd_W1 = (const float*)d_in[13];
    const float* upd_b1 = (const float*)d_in[14];
    const float* upd_W2 = (const float*)d_in[15];
    const float* upd_b2 = (const float*)d_in[16];
    const float* pred_W1 = (const float*)d_in[17];
    const float* pred_b1 = (const float*)d_in[18];
    const float* pred_W2 = (const float*)d_in[19];
    const float* pred_b2 = (const float*)d_in[20];
    const float* pred_W3 = (const float*)d_in[21];
    const float* pred_b3 = (const float*)d_in[22];

    int NE = in_sizes[0] / 64;
    int NA = in_sizes[1];
    int NC = in_sizes[3];
    if (NE > NE_MAX) NE = NE_MAX;

    float *Hagg, *bc;
    int* deg;
    u16 *eh, *el, *e2h, *e2l, *hh, *hl, *wh, *wl, *Pq, *Qq;
    cudaGetSymbolAddress((void**)&Pq,   g_Pq);
    cudaGetSymbolAddress((void**)&Qq,   g_Qq);
    cudaGetSymbolAddress((void**)&Hagg, g_agg);
    cudaGetSymbolAddress((void**)&deg,  g_deg);
    cudaGetSymbolAddress((void**)&bc,   g_bc);
    cudaGetSymbolAddress((void**)&eh,   g_eh);
    cudaGetSymbolAddress((void**)&el,   g_el);
    cudaGetSymbolAddress((void**)&e2h,  g_e2h);
    cudaGetSymbolAddress((void**)&e2l,  g_e2l);
    cudaGetSymbolAddress((void**)&hh,   g_hh);
    cudaGetSymbolAddress((void**)&hl,   g_hl);
    cudaGetSymbolAddress((void**)&wh,   g_wh);
    cudaGetSymbolAddress((void**)&wl,   g_wl);

    cudaFuncSetAttribute(gk_enc,   cudaFuncAttributeMaxDynamicSharedMemorySize, D_SMEM_BYTES);
    cudaFuncSetAttribute(gk_plain, cudaFuncAttributeMaxDynamicSharedMemorySize, SMEM_BYTES);
    cudaFuncSetAttribute(gk_dual,  cudaFuncAttributeMaxDynamicSharedMemorySize, D_SMEM_BYTES);
    cudaFuncSetAttribute(gk_upd,   cudaFuncAttributeMaxDynamicSharedMemorySize, D_SMEM_BYTES);
    cudaFuncSetAttribute(gk_pair,  cudaFuncAttributeMaxDynamicSharedMemorySize, SMEM_BYTES);

    cudaMemsetAsync(deg, 0, (size_t)NE * sizeof(int));
    cudaMemsetAsync(Hagg, 0, (size_t)NE * H * sizeof(float));   // once; gk_upd recycles
    deg_kernel<<<(NA + 255) / 256, 256>>>(adj_dst, NA, deg);

    // ---- weight prep ----
    PJobs pj;
    int cursor = 0, nj = 0;
    auto addjob = [&](const float* W, int ro, int K, int off) {
        pj.W[nj] = W; pj.rowoff[nj] = ro; pj.K[nj] = K; pj.off[nj] = off;
        pj.start[nj] = cursor; cursor += 128 * K; nj++;
    };
    addjob(enc_W1, 0, 64, OFF_ENC1);
    addjob(enc_W2, 0, 128, OFF_ENC2);
    for (int l = 0; l < 3; l++) {
        const float* mW1 = msg_W1 + (size_t)l * 2 * H * H;
        const float* uW1 = upd_W1 + (size_t)l * 2 * H * H;
        const float* uW2 = upd_W2 + (size_t)l * H * H;
        addjob(mW1, 0,   128, OFF_W1T(l));
        addjob(mW1, 128, 128, OFF_W1B(l));
        addjob(uW1, 0,   128, OFF_U1T(l));
        addjob(uW2, 0,   128, OFF_UW2(l));
    }
    addjob(pred_W1, 0,   128, OFF_P1T);
    addjob(pred_W1, 128, 128, OFF_P1B);
    addjob(pred_W2, 0,   128, OFF_P2);
    pj.njobs = nj; pj.total = cursor;
    prep_all<<<(cursor + 255) / 256, 256>>>(pj);
    compprep<<<195, 256>>>(upd_W1, msg_W2, msg_b2, upd_b1);

    int gNE = (NE + 63) / 64;
    int gNC = (NC + 63) / 64;
    int gE = gNE < 148 ? gNE : 148;
    int gC = gNC < 148 ? gNC : 148;

    // fused encoder
    gk_enc<<<gE, 512, D_SMEM_BYTES>>>(
        feat, wh + OFF_ENC1, wl + OFF_ENC1, wh + OFF_ENC2, wl + OFF_ENC2,
        enc_b1, enc_b2, eh, el, NE, gNE);

    u16 *ch = eh, *cl = el, *nh = e2h, *nl = e2l;
    for (int l = 0; l < 3; l++) {
        const float* mb1 = msg_b1 + (size_t)l * H;
        const float* ub2 = upd_b2 + (size_t)l * H;

        gk_dual<<<gE, 512, D_SMEM_BYTES>>>(
            ch, cl, wh + OFF_W1T(l), wl + OFF_W1T(l),
            wh + OFF_W1B(l), wl + OFF_W1B(l), Pq, Qq, NE, gNE);

        msum<<<(NA + 127) / 128, 256>>>(Pq, Qq, mb1, adj_dst, adj_src, Hagg, NA);

        gk_upd<<<gE, 512, D_SMEM_BYTES>>>(
            ch, cl, Hagg, Pq, Qq, mb1,
            wh + OFF_U1T(l), wl + OFF_U1T(l), wh + OFF_WC(l), wl + OFF_WC(l),
            bc + l * H, deg, hh, hl, NE, gNE);

        gk_plain<<<gE, 512, SMEM_BYTES>>>(
            hh, hl, wh + OFF_UW2(l), wl + OFF_UW2(l),
            ub2, nh, nl, NE, gNE);

        u16* t1 = ch; ch = nh; nh = t1;
        u16* t2 = cl; cl = nl; nl = t2;
    }

    gk_dual<<<gE, 512, D_SMEM_BYTES>>>(
        ch, cl, wh + OFF_P1T, wl + OFF_P1T,
        wh + OFF_P1B, wl + OFF_P1B, Pq, Qq, NE, gNE);
    int logit_off = (out_size >= 2 * NC) ? NC : -1;
    gk_pair<<<gC, 512, SMEM_BYTES>>>(
        Pq, Qq, cand_i, cand_j, wh + OFF_P2, wl + OFF_P2,
        pred_b1, pred_b2, pred_W3, pred_b3,
        (float*)d_out, NC, gNC, logit_off);
}

// round 16
// speedup vs baseline: 1.0089x; 1.0038x over previous
#include <cuda_runtime.h>
#include <cuda_bf16.h>
#include <cuda_fp16.h>
#include <stdint.h>
#include <math.h>

#define H 128
#define NE_MAX 50000

typedef unsigned int uint;
typedef unsigned short u16;

// ---------------- device scratch (allocation-free rule) ----------------
__device__ u16   g_eh [NE_MAX * H];
__device__ u16   g_el [NE_MAX * H];
__device__ u16   g_e2h[NE_MAX * H];
__device__ u16   g_e2l[NE_MAX * H];
__device__ u16   g_hh [NE_MAX * H];
__device__ u16   g_hl [NE_MAX * H];
__device__ u16   g_Pq [NE_MAX * H];      // fp16 P
__device__ u16   g_Qq [NE_MAX * H];      // fp16 Q
__device__ float g_agg[NE_MAX * H];
__device__ int   g_deg[NE_MAX];
__device__ float g_bc [3 * H];
#define WSCRATCH 368640
__device__ u16 g_wh[WSCRATCH];
__device__ u16 g_wl[WSCRATCH];

// transposed/split weight offsets (elements)
#define OFF_ENC1 0
#define OFF_ENC2 8192
#define OFF_L(l)   (24576 + (l) * 98304)
#define OFF_W1T(l) (OFF_L(l))
#define OFF_W1B(l) (OFF_L(l) + 16384)
#define OFF_WC(l)  (OFF_L(l) + 32768)
#define OFF_U1T(l) (OFF_L(l) + 49152)
#define OFF_UW2(l) (OFF_L(l) + 81920)
#define OFF_P1T 319488
#define OFF_P1B 335872
#define OFF_P2  352256

// ---- single-GEMM smem layout ----
#define WROW 68
#define WH_W 0
#define WL_W 8704
#define ABASE 17408
#define ABUF  8704
#define AHALF 4352
#define CTRL_W 34816
#define SMEM_WORDS 35104
#define SMEM_BYTES (SMEM_WORDS * 4)

// ---- dual-GEMM smem layout ----
#define D_W1H 0
#define D_W1L 8704
#define D_W2H 17408
#define D_W2L 26112
#define D_ABASE 34816
#define D_ABUF  8704
#define D_AHALF 4352
#define D_SMEM_WORDS 52224
#define D_SMEM_BYTES (D_SMEM_WORDS * 4)

// ---------------- helpers ----------------
__device__ __forceinline__ uint phi(float a, float b) {
    return (uint)__bfloat16_as_ushort(__float2bfloat16_rn(a))
         | ((uint)__bfloat16_as_ushort(__float2bfloat16_rn(b)) << 16);
}
__device__ __forceinline__ uint plo(float a, float b) {
    float ah = __bfloat162float(__float2bfloat16_rn(a));
    float bh = __bfloat162float(__float2bfloat16_rn(b));
    return phi(a - ah, b - bh);
}
__device__ __forceinline__ uint h2u(float a, float b) {
    __half2 h = __floats2half2_rn(a, b);
    return *(uint*)&h;
}
__device__ __forceinline__ float2 u2f(uint u) {
    return __half22float2(*(const __half2*)&u);
}
__device__ __forceinline__ uint smem_u32(const void* p) {
    uint a;
    asm("{ .reg .u64 t; cvta.to.shared.u64 t, %1; cvt.u32.u64 %0, t; }" : "=r"(a) : "l"(p));
    return a;
}
__device__ __forceinline__ void cpa16(uint dst, const void* src) {
    asm volatile("cp.async.cg.shared.global [%0], [%1], 16;" :: "r"(dst), "l"(src));
}
#define CPA_COMMIT() asm volatile("cp.async.commit_group;" ::: "memory")
#define CPA_WAIT(n)  asm volatile("cp.async.wait_group %0;" :: "n"(n) : "memory")

__device__ __forceinline__ void mma_bf(float* c, uint a0, uint a1, uint a2, uint a3,
                                       uint b0, uint b1) {
    asm volatile(
        "mma.sync.aligned.m16n8k16.row.col.f32.bf16.bf16.f32 "
        "{%0,%1,%2,%3},{%4,%5,%6,%7},{%8,%9},{%0,%1,%2,%3};"
        : "+f"(c[0]), "+f"(c[1]), "+f"(c[2]), "+f"(c[3])
        : "r"(a0), "r"(a1), "r"(a2), "r"(a3), "r"(b0), "r"(b1));
}
__device__ __forceinline__ void ldsm4(uint& r0, uint& r1, uint& r2, uint& r3, uint addr) {
    asm volatile("ldmatrix.sync.aligned.m8n8.x4.shared.b16 {%0,%1,%2,%3}, [%4];"
        : "=r"(r0), "=r"(r1), "=r"(r2), "=r"(r3) : "r"(addr));
}

// warp tile 16x32 via ldmatrix; 16 warps = 4(M) x 4(N); M-tile 64, N 128
template <int NK>
__device__ __forceinline__ void gemm_core_lm(uint sb, int aH, int aL, int wH, int wL,
                                             float acc[4][4], int wm, int wn, int lane) {
    const int l7 = lane & 7, lm = lane >> 3;
    const int radd = (lm & 1) * 8;
    const int koff = (lm >> 1) * 4;
    uint aBh  = sb + ((uint)(aH + (wm + l7 + radd) * WROW + koff) << 2);
    uint aBl  = sb + ((uint)(aL + (wm + l7 + radd) * WROW + koff) << 2);
    uint bBh0 = sb + ((uint)(wH + (wn + l7 + radd) * WROW + koff) << 2);
    uint bBl0 = sb + ((uint)(wL + (wn + l7 + radd) * WROW + koff) << 2);
    uint bBh1 = bBh0 + 16 * WROW * 4;
    uint bBl1 = bBl0 + 16 * WROW * 4;
#pragma unroll
    for (int ks = 0; ks < NK; ks++) {
        uint ko = ks * 32;
        uint ah0, ah1, ah2, ah3, al0, al1, al2, al3;
        ldsm4(ah0, ah1, ah2, ah3, aBh + ko);
        ldsm4(al0, al1, al2, al3, aBl + ko);
        uint p0, p1, p2, p3, q0, q1, q2, q3;
        ldsm4(p0, p1, p2, p3, bBh0 + ko);
        ldsm4(q0, q1, q2, q3, bBh1 + ko);
        uint u0, u1, u2, u3, v0, v1, v2, v3;
        ldsm4(u0, u1, u2, u3, bBl0 + ko);
        ldsm4(v0, v1, v2, v3, bBl1 + ko);
        mma_bf(acc[0], ah0, ah1, ah2, ah3, p0, p2);
        mma_bf(acc[1], ah0, ah1, ah2, ah3, p1, p3);
        mma_bf(acc[2], ah0, ah1, ah2, ah3, q0, q2);
        mma_bf(acc[3], ah0, ah1, ah2, ah3, q1, q3);
        mma_bf(acc[0], ah0, ah1, ah2, ah3, u0, u2);
        mma_bf(acc[1], ah0, ah1, ah2, ah3, u1, u3);
        mma_bf(acc[2], ah0, ah1, ah2, ah3, v0, v2);
        mma_bf(acc[3], ah0, ah1, ah2, ah3, v1, v3);
        mma_bf(acc[0], al0, al1, al2, al3, p0, p2);
        mma_bf(acc[1], al0, al1, al2, al3, p1, p3);
        mma_bf(acc[2], al0, al1, al2, al3, q0, q2);
        mma_bf(acc[3], al0, al1, al2, al3, q1, q3);
    }
}

template <int NK>
__device__ __forceinline__ void load_weights(uint* sm, int dH, int dL,
                                             const u16* Wth, const u16* Wtl, int tid) {
    const int nv = 128 * NK * 2;
    const uint4* sh = (const uint4*)Wth;
    const uint4* sl = (const uint4*)Wtl;
    for (int i = tid; i < nv; i += 512) {
        int n = i / (NK * 2), q = i % (NK * 2);
        *(uint4*)(sm + dH + n * WROW + q * 4) = sh[i];
        *(uint4*)(sm + dL + n * WROW + q * 4) = sl[i];
    }
}

// ---------------- small kernels ----------------
__global__ void deg_kernel(const int* __restrict__ dst, int na, int* __restrict__ deg) {
    int i = blockIdx.x * blockDim.x + threadIdx.x;
    if (i < na) atomicAdd(&deg[dst[i]], 1);
}

struct PJobs {
    const float* W[20];
    int rowoff[20], K[20], off[20], start[20];
    int njobs, total;
};
__global__ void prep_all(PJobs j) {
    int i = blockIdx.x * 256 + threadIdx.x;
    if (i >= j.total) return;
    int a = 0;
    while (a + 1 < j.njobs && i >= j.start[a + 1]) a++;
    int e = i - j.start[a];
    int K = j.K[a];
    int n = e / K, k = e % K;
    float v = j.W[a][(size_t)(j.rowoff[a] + k) * 128 + n];
    __nv_bfloat16 h = __float2bfloat16_rn(v);
    g_wh[j.off[a] + e] = __bfloat16_as_ushort(h);
    g_wl[j.off[a] + e] = __bfloat16_as_ushort(__float2bfloat16_rn(v - __bfloat162float(h)));
}

__global__ void compprep(const float* __restrict__ upd_W1,
                         const float* __restrict__ msg_W2,
                         const float* __restrict__ msg_b2,
                         const float* __restrict__ upd_b1) {
    int b = blockIdx.x;
    if (b < 192) {
        int l = b >> 6;
        int i = (b & 63) * 256 + threadIdx.x;
        int o = i & 127, h = i >> 7;
        const float* W2  = msg_W2 + (size_t)l * 16384;
        const float* U1b = upd_W1 + (size_t)l * 32768 + 16384;
        float s = 0.f;
        for (int a2 = 0; a2 < 128; a2++) s += W2[h * 128 + a2] * U1b[a2 * 128 + o];
        int li = OFF_WC(l) + o * 128 + h;
        __nv_bfloat16 hh = __float2bfloat16_rn(s);
        g_wh[li] = __bfloat16_as_ushort(hh);
        g_wl[li] = __bfloat16_as_ushort(__float2bfloat16_rn(s - __bfloat162float(hh)));
    } else if (b < 195) {
        int l = b - 192;
        int o = threadIdx.x;
        if (o < 128) {
            const float* U1b = upd_W1 + (size_t)l * 32768 + 16384;
            const float* b2  = msg_b2 + (size_t)l * 128;
            float s = upd_b1[l * 128 + o];
            for (int a2 = 0; a2 < 128; a2++) s += b2[a2] * U1b[a2 * 128 + o];
            g_bc[l * 128 + o] = s;
        }
    }
}

// pair hidden aggregation: Hagg[dst] += ReLU(P[dst] + Q[src] + b1)  (P,Q fp16)
__global__ __launch_bounds__(256) void msum(const u16* __restrict__ P,
                                            const u16* __restrict__ Q,
                                            const float* __restrict__ b1,
                                            const int* __restrict__ dst,
                                            const int* __restrict__ src,
                                            float* __restrict__ Hagg, int na) {
    int team = threadIdx.x >> 7, col = threadIdx.x & 127;
    int p0 = blockIdx.x * 128 + team * 64;
    if (p0 >= na) return;
    float bias = __ldg(&b1[col]);
    float sum = 0.f, pv = 0.f;
    int cur = -1;
    for (int base = 0; base < 64; base += 8) {
        int dd[8], ss[8];
#pragma unroll
        for (int j = 0; j < 8; j++) {
            int a = p0 + base + j;
            bool v = a < na;
            dd[j] = v ? __ldg(&dst[a]) : -1;
            ss[j] = v ? __ldg(&src[a]) : 0;
        }
        float qv[8];
#pragma unroll
        for (int j = 0; j < 8; j++)
            qv[j] = __half2float(((const __half*)Q)[(size_t)ss[j] * H + col]);
#pragma unroll
        for (int j = 0; j < 8; j++) {
            if (dd[j] != cur) {
                if (cur >= 0) atomicAdd(&Hagg[(size_t)cur * H + col], sum);
                cur = dd[j];
                sum = 0.f;
                if (cur >= 0)
                    pv = __half2float(((const __half*)P)[(size_t)cur * H + col]) + bias;
            }
            if (dd[j] >= 0) sum += fmaxf(pv + qv[j], 0.f);
        }
    }
    if (cur >= 0) atomicAdd(&Hagg[(size_t)cur * H + col], sum);
}

// ---------------- fused encoder ----------------
__global__ __launch_bounds__(512, 1)
void gk_enc(const float* __restrict__ feat,
            const u16* __restrict__ W1h_, const u16* __restrict__ W1l_,
            const u16* __restrict__ W2h_, const u16* __restrict__ W2l_,
            const float* __restrict__ b1, const float* __restrict__ b2,
            u16* __restrict__ obh, u16* __restrict__ obl,
            int nrows, int ntiles)
{
    extern __shared__ uint sm[];
    const int tid = threadIdx.x;
    const int lane = tid & 31, w = tid >> 5;
    const int wm = (w & 3) * 16, wn = (w >> 2) * 32;
    const uint sb = smem_u32(sm);
    const int HID = D_ABASE + D_ABUF;

    load_weights<4>(sm, D_W1H, D_W1L, W1h_, W1l_, tid);
    load_weights<8>(sm, D_W2H, D_W2L, W2h_, W2l_, tid);

    const int r8 = tid >> 3, c8 = tid & 7;
    const int lg = lane >> 2, lt = lane & 3;

    for (int t = blockIdx.x; t < ntiles; t += gridDim.x) {
        const int t0 = t * 64;
        __syncthreads();
        {
            int gr = t0 + r8;
            int rr = (gr < nrows) ? gr : 0;
            const float4* s = (const float4*)(feat + (size_t)rr * 64) + c8 * 2;
            int base = D_ABASE + r8 * WROW + c8 * 4;
#pragma unroll
            for (int q = 0; q < 2; q++) {
                float4 v = s[q];
                *(uint2*)(sm + base + 2 * q)           = make_uint2(phi(v.x, v.y), phi(v.z, v.w));
                *(uint2*)(sm + base + D_AHALF + 2 * q) = make_uint2(plo(v.x, v.y), plo(v.z, v.w));
            }
        }
        __syncthreads();

        float acc[4][4];
#pragma unroll
        for (int nf = 0; nf < 4; nf++)
#pragma unroll
            for (int q = 0; q < 4; q++) acc[nf][q] = 0.f;
        gemm_core_lm<4>(sb, D_ABASE, D_ABASE + D_AHALF, D_W1H, D_W1L, acc, wm, wn, lane);

#pragma unroll
        for (int nf = 0; nf < 4; nf++) {
            int row = wm + lg;
            int col = wn + nf * 8 + lt * 2;
            float b0 = __ldg(&b1[col]), b1v = __ldg(&b1[col + 1]);
            float v0 = fmaxf(acc[nf][0] + b0, 0.f);
            float v1 = fmaxf(acc[nf][1] + b1v, 0.f);
            float v2 = fmaxf(acc[nf][2] + b0, 0.f);
            float v3 = fmaxf(acc[nf][3] + b1v, 0.f);
            int wi = col >> 1;
            sm[HID + row * WROW + wi]                 = phi(v0, v1);
            sm[HID + D_AHALF + row * WROW + wi]       = plo(v0, v1);
            sm[HID + (row + 8) * WROW + wi]           = phi(v2, v3);
            sm[HID + D_AHALF + (row + 8) * WROW + wi] = plo(v2, v3);
        }
        __syncthreads();

#pragma unroll
        for (int nf = 0; nf < 4; nf++)
#pragma unroll
            for (int q = 0; q < 4; q++) acc[nf][q] = 0.f;
        gemm_core_lm<8>(sb, HID, HID + D_AHALF, D_W2H, D_W2L, acc, wm, wn, lane);

#pragma unroll
        for (int nf = 0; nf < 4; nf++) {
            int row = wm + lg;
            int col = wn + nf * 8 + lt * 2;
            int g0 = t0 + row, g1 = g0 + 8;
            float b0 = __ldg(&b2[col]), b1v = __ldg(&b2[col + 1]);
            float v0 = acc[nf][0] + b0, v1 = acc[nf][1] + b1v;
            float v2 = acc[nf][2] + b0, v3 = acc[nf][3] + b1v;
            int wi = col >> 1;
            if (g0 < nrows) {
                ((uint*)obh)[(size_t)g0 * 64 + wi] = phi(v0, v1);
                ((uint*)obl)[(size_t)g0 * 64 + wi] = plo(v0, v1);
            }
            if (g1 < nrows) {
                ((uint*)obh)[(size_t)g1 * 64 + wi] = phi(v2, v3);
                ((uint*)obl)[(size_t)g1 * 64 + wi] = plo(v2, v3);
            }
        }
    }
}

// ---------------- single GEMM (bf16 in, cp.async double-buffer), bias+ReLU -> bf16 ----------------
__global__ __launch_bounds__(512, 1)
void gk_plain(const u16* __restrict__ Aph, const u16* __restrict__ Apl,
              const u16* __restrict__ Wth, const u16* __restrict__ Wtl,
              const float* __restrict__ bias,
              u16* __restrict__ obh, u16* __restrict__ obl,
              int nrows, int ntiles)
{
    extern __shared__ uint sm[];
    const int tid = threadIdx.x;
    const int lane = tid & 31, w = tid >> 5;
    const int wm = (w & 3) * 16, wn = (w >> 2) * 32;
    const uint sb = smem_u32(sm);

    load_weights<8>(sm, WH_W, WL_W, Wth, Wtl, tid);

    const int r8 = tid >> 3, c8 = tid & 7;

    auto fill_async = [&](int t, int p) {
        int gr = t * 64 + r8;
        int rr = (gr < nrows) ? gr : 0;
        const char* shp = (const char*)(Aph + (size_t)rr * H) + c8 * 16;
        const char* slp = (const char*)(Apl + (size_t)rr * H) + c8 * 16;
        uint dh = sb + (ABASE + p * ABUF + r8 * WROW + c8 * 4) * 4;
        uint dl = dh + AHALF * 4;
        cpa16(dh, shp);        cpa16(dh + 128, shp + 128);
        cpa16(dl, slp);        cpa16(dl + 128, slp + 128);
        CPA_COMMIT();
    };

    int p = 0;
    fill_async(blockIdx.x < ntiles ? blockIdx.x : 0, 0);

    for (int t = blockIdx.x; t < ntiles; t += gridDim.x) {
        __syncthreads();
        int tn = t + gridDim.x;
        fill_async(tn < ntiles ? tn : t, p ^ 1);
        CPA_WAIT(1);
        __syncthreads();

        float acc[4][4];
#pragma unroll
        for (int nf = 0; nf < 4; nf++)
#pragma unroll
            for (int q = 0; q < 4; q++) acc[nf][q] = 0.f;
        int aH = ABASE + p * ABUF;
        gemm_core_lm<8>(sb, aH, aH + AHALF, WH_W, WL_W, acc, wm, wn, lane);

        const int t0 = t * 64;
        const int lg = lane >> 2, lt = lane & 3;
#pragma unroll
        for (int nf = 0; nf < 4; nf++) {
            int row = wm + lg;
            int col = wn + nf * 8 + lt * 2;
            int g0 = t0 + row, g1 = g0 + 8;
            float b0 = __ldg(&bias[col]), b1v = __ldg(&bias[col + 1]);
            float v0 = fmaxf(acc[nf][0] + b0, 0.f);
            float v1 = fmaxf(acc[nf][1] + b1v, 0.f);
            float v2 = fmaxf(acc[nf][2] + b0, 0.f);
            float v3 = fmaxf(acc[nf][3] + b1v, 0.f);
            int wi = col >> 1;
            if (g0 < nrows) {
                ((uint*)obh)[(size_t)g0 * 64 + wi] = phi(v0, v1);
                ((uint*)obl)[(size_t)g0 * 64 + wi] = plo(v0, v1);
            }
            if (g1 < nrows) {
                ((uint*)obh)[(size_t)g1 * 64 + wi] = phi(v2, v3);
                ((uint*)obl)[(size_t)g1 * 64 + wi] = plo(v2, v3);
            }
        }
        p ^= 1;
    }
}

// ---------------- dual GEMM, shared A: out1 = A@W1, out2 = A@W2 -> fp16 ----------------
__global__ __launch_bounds__(512, 1)
void gk_dual(const u16* __restrict__ Aph, const u16* __restrict__ Apl,
             const u16* __restrict__ W1h_, const u16* __restrict__ W1l_,
             const u16* __restrict__ W2h_, const u16* __restrict__ W2l_,
             u16* __restrict__ out1, u16* __restrict__ out2,
             int nrows, int ntiles)
{
    extern __shared__ uint sm[];
    const int tid = threadIdx.x;
    const int lane = tid & 31, w = tid >> 5;
    const int wm = (w & 3) * 16, wn = (w >> 2) * 32;
    const uint sb = smem_u32(sm);

    load_weights<8>(sm, D_W1H, D_W1L, W1h_, W1l_, tid);
    load_weights<8>(sm, D_W2H, D_W2L, W2h_, W2l_, tid);

    const int r8 = tid >> 3, c8 = tid & 7;
    auto fill_async = [&](int t, int p) {
        int gr = t * 64 + r8;
        int rr = (gr < nrows) ? gr : 0;
        const char* shp = (const char*)(Aph + (size_t)rr * H) + c8 * 16;
        const char* slp = (const char*)(Apl + (size_t)rr * H) + c8 * 16;
        uint dh = sb + (D_ABASE + p * D_ABUF + r8 * WROW + c8 * 4) * 4;
        uint dl = dh + D_AHALF * 4;
        cpa16(dh, shp);        cpa16(dh + 128, shp + 128);
        cpa16(dl, slp);        cpa16(dl + 128, slp + 128);
        CPA_COMMIT();
    };

    int p = 0;
    fill_async(blockIdx.x < ntiles ? blockIdx.x : 0, 0);

    for (int t = blockIdx.x; t < ntiles; t += gridDim.x) {
        __syncthreads();
        int tn = t + gridDim.x;
        fill_async(tn < ntiles ? tn : t, p ^ 1);
        CPA_WAIT(1);
        __syncthreads();

        int aH = D_ABASE + p * D_ABUF;
        float acc1[4][4], acc2[4][4];
#pragma unroll
        for (int nf = 0; nf < 4; nf++)
#pragma unroll
            for (int q = 0; q < 4; q++) { acc1[nf][q] = 0.f; acc2[nf][q] = 0.f; }
        gemm_core_lm<8>(sb, aH, aH + D_AHALF, D_W1H, D_W1L, acc1, wm, wn, lane);
        gemm_core_lm<8>(sb, aH, aH + D_AHALF, D_W2H, D_W2L, acc2, wm, wn, lane);

        const int t0 = t * 64;
        const int lg = lane >> 2, lt = lane & 3;
#pragma unroll
        for (int nf = 0; nf < 4; nf++) {
            int row = wm + lg;
            int col = wn + nf * 8 + lt * 2;
            int g0 = t0 + row, g1 = g0 + 8;
            int wi = col >> 1;
            if (g0 < nrows) {
                ((uint*)out1)[(size_t)g0 * 64 + wi] = h2u(acc1[nf][0], acc1[nf][1]);
                ((uint*)out2)[(size_t)g0 * 64 + wi] = h2u(acc2[nf][0], acc2[nf][1]);
            }
            if (g1 < nrows) {
                ((uint*)out1)[(size_t)g1 * 64 + wi] = h2u(acc1[nf][2], acc1[nf][3]);
                ((uint*)out2)[(size_t)g1 * 64 + wi] = h2u(acc2[nf][2], acc2[nf][3]);
            }
        }
        p ^= 1;
    }
}

// ---------------- update fused: hid = ReLU(e@U1T + (Hagg*inv_deg)@WC + bias) -> bf16 ----------------
// deg==0 rows: A2 = ReLU(P+Q+mb1) inline (replaces fixup kernel)
__global__ __launch_bounds__(512, 1)
void gk_upd(const u16* __restrict__ Aph, const u16* __restrict__ Apl,
            const float* __restrict__ Hagg,
            const u16* __restrict__ Pq, const u16* __restrict__ Qq,
            const float* __restrict__ mb1,
            const u16* __restrict__ W1h_, const u16* __restrict__ W1l_,
            const u16* __restrict__ W2h_, const u16* __restrict__ W2l_,
            const float* __restrict__ bias, const int* __restrict__ deg,
            u16* __restrict__ obh, u16* __restrict__ obl,
            int nrows, int ntiles)
{
    extern __shared__ uint sm[];
    const int tid = threadIdx.x;
    const int lane = tid & 31, w = tid >> 5;
    const int wm = (w & 3) * 16, wn = (w >> 2) * 32;
    const uint sb = smem_u32(sm);

    load_weights<8>(sm, D_W1H, D_W1L, W1h_, W1l_, tid);
    load_weights<8>(sm, D_W2H, D_W2L, W2h_, W2l_, tid);

    const int r8 = tid >> 3, c8 = tid & 7;

    for (int t = blockIdx.x; t < ntiles; t += gridDim.x) {
        const int t0 = t * 64;
        int gr = t0 + r8;
        int rr = (gr < nrows) ? gr : 0;
        __syncthreads();
        {   // A1: e via cp.async
            const char* shp = (const char*)(Aph + (size_t)rr * H) + c8 * 16;
            const char* slp = (const char*)(Apl + (size_t)rr * H) + c8 * 16;
            uint dh = sb + (D_ABASE + r8 * WROW + c8 * 4) * 4;
            uint dl = dh + D_AHALF * 4;
            cpa16(dh, shp);        cpa16(dh + 128, shp + 128);
            cpa16(dl, slp);        cpa16(dl + 128, slp + 128);
            CPA_COMMIT();
        }
        {   // A2: Hagg * inv_deg  (or iso: ReLU(P+Q+mb1))
            int d = deg[rr];
            int base = D_ABASE + D_ABUF + r8 * WROW + c8 * 8;
            float vals[16];
            if (d == 0) {
                const uint4* pp = (const uint4*)(Pq + (size_t)rr * H + c8 * 16);
                const uint4* qq = (const uint4*)(Qq + (size_t)rr * H + c8 * 16);
#pragma unroll
                for (int q = 0; q < 2; q++) {
                    uint4 xv = pp[q], yv = qq[q];
                    uint xu[4] = {xv.x, xv.y, xv.z, xv.w};
                    uint yu[4] = {yv.x, yv.y, yv.z, yv.w};
#pragma unroll
                    for (int k = 0; k < 4; k++) {
                        float2 fx = u2f(xu[k]), fy = u2f(yu[k]);
                        int c = c8 * 16 + q * 8 + k * 2;
                        vals[q * 8 + k * 2]     = fmaxf(fx.x + fy.x + __ldg(&mb1[c]),     0.f);
                        vals[q * 8 + k * 2 + 1] = fmaxf(fx.y + fy.y + __ldg(&mb1[c + 1]), 0.f);
                    }
                }
            } else {
                float sc = 1.f / (d > 1 ? (float)d : 1.f);
                const float4* s = (const float4*)(Hagg + (size_t)rr * H) + c8 * 4;
#pragma unroll
                for (int q = 0; q < 4; q++) {
                    float4 v = s[q];
                    vals[4*q] = v.x*sc; vals[4*q+1] = v.y*sc; vals[4*q+2] = v.z*sc; vals[4*q+3] = v.w*sc;
                }
            }
#pragma unroll
            for (int q = 0; q < 4; q++) {
                *(uint2*)(sm + base + 2 * q) =
                    make_uint2(phi(vals[4*q], vals[4*q+1]), phi(vals[4*q+2], vals[4*q+3]));
                *(uint2*)(sm + base + D_AHALF + 2 * q) =
                    make_uint2(plo(vals[4*q], vals[4*q+1]), plo(vals[4*q+2], vals[4*q+3]));
            }
        }
        CPA_WAIT(0);
        __syncthreads();

        float acc[4][4];
#pragma unroll
        for (int nf = 0; nf < 4; nf++)
#pragma unroll
            for (int q = 0; q < 4; q++) acc[nf][q] = 0.f;
        gemm_core_lm<8>(sb, D_ABASE, D_ABASE + D_AHALF, D_W1H, D_W1L, acc, wm, wn, lane);
        gemm_core_lm<8>(sb, D_ABASE + D_ABUF, D_ABASE + D_ABUF + D_AHALF, D_W2H, D_W2L, acc, wm, wn, lane);

        const int lg = lane >> 2, lt = lane & 3;
#pragma unroll
        for (int nf = 0; nf < 4; nf++) {
            int row = wm + lg;
            int col = wn + nf * 8 + lt * 2;
            int g0 = t0 + row, g1 = g0 + 8;
            float b0 = __ldg(&bias[col]), b1v = __ldg(&bias[col + 1]);
            float v0 = fmaxf(acc[nf][0] + b0, 0.f);
            float v1 = fmaxf(acc[nf][1] + b1v, 0.f);
            float v2 = fmaxf(acc[nf][2] + b0, 0.f);
            float v3 = fmaxf(acc[nf][3] + b1v, 0.f);
            int wi = col >> 1;
            if (g0 < nrows) {
                ((uint*)obh)[(size_t)g0 * 64 + wi] = phi(v0, v1);
                ((uint*)obl)[(size_t)g0 * 64 + wi] = plo(v0, v1);
            }
            if (g1 < nrows) {
                ((uint*)obh)[(size_t)g1 * 64 + wi] = phi(v2, v3);
                ((uint*)obl)[(size_t)g1 * 64 + wi] = plo(v2, v3);
            }
        }
    }
}

// ---------------- pairsum GEMM + predictor epilogue (X,Y fp16) ----------------
__global__ __launch_bounds__(512, 1)
void gk_pair(const u16* __restrict__ X, const u16* __restrict__ Y,
             const int* __restrict__ idx0, const int* __restrict__ idx1,
             const u16* __restrict__ Wth, const u16* __restrict__ Wtl,
             const float* __restrict__ b1, const float* __restrict__ b2,
             const float* __restrict__ W3, const float* __restrict__ b3,
             float* __restrict__ pout,
             int nrows, int ntiles, int logit_off)
{
    extern __shared__ uint sm[];
    float* sp = (float*)(sm + CTRL_W);

    const int tid = threadIdx.x;
    const int lane = tid & 31, w = tid >> 5;
    const int wm = (w & 3) * 16, wn = (w >> 2) * 32;
    const uint sb = smem_u32(sm);

    load_weights<8>(sm, WH_W, WL_W, Wth, Wtl, tid);

    const int r8 = tid >> 3, c8 = tid & 7;

    for (int t = blockIdx.x; t < ntiles; t += gridDim.x) {
        const int t0 = t * 64;
        {
            int gr = t0 + r8;
            int rr = (gr < nrows) ? gr : 0;
            int i0 = __ldg(&idx0[rr]);
            int i1 = __ldg(&idx1[rr]);
            int ch = c8 * 16;
            const uint4* xp = (const uint4*)(X + (size_t)i0 * H + ch);
            const uint4* yp = (const uint4*)(Y + (size_t)i1 * H + ch);
            int base = ABASE + r8 * WROW + c8 * 8;
            __syncthreads();
#pragma unroll
            for (int q = 0; q < 2; q++) {
                uint4 xv = xp[q], yv = yp[q];
                uint xu[4] = {xv.x, xv.y, xv.z, xv.w};
                uint yu[4] = {yv.x, yv.y, yv.z, yv.w};
                float v[8];
#pragma unroll
                for (int k = 0; k < 4; k++) {
                    float2 fx = u2f(xu[k]), fy = u2f(yu[k]);
                    int c = ch + q * 8 + k * 2;
                    v[2*k]     = fmaxf(fx.x + fy.x + __ldg(&b1[c]),     0.f);
                    v[2*k + 1] = fmaxf(fx.y + fy.y + __ldg(&b1[c + 1]), 0.f);
                }
#pragma unroll
                for (int k = 0; k < 4; k++) {
                    sm[base + q * 4 + k]         = phi(v[2*k], v[2*k+1]);
                    sm[base + AHALF + q * 4 + k] = plo(v[2*k], v[2*k+1]);
                }
            }
        }
        __syncthreads();

        float acc[4][4];
#pragma unroll
        for (int nf = 0; nf < 4; nf++)
#pragma unroll
            for (int q = 0; q < 4; q++) acc[nf][q] = 0.f;
        gemm_core_lm<8>(sb, ABASE, ABASE + AHALF, WH_W, WL_W, acc, wm, wn, lane);

        const int lg = lane >> 2, lt = lane & 3;
        float p0 = 0.f, p1 = 0.f;
#pragma unroll
        for (int nf = 0; nf < 4; nf++) {
            int col = wn + nf * 8 + lt * 2;
            float b0 = __ldg(&b2[col]), b1v = __ldg(&b2[col + 1]);
            float w30 = __ldg(&W3[col]), w31 = __ldg(&W3[col + 1]);
            p0 += fmaxf(acc[nf][0] + b0, 0.f) * w30
                + fmaxf(acc[nf][1] + b1v, 0.f) * w31;
            p1 += fmaxf(acc[nf][2] + b0, 0.f) * w30
                + fmaxf(acc[nf][3] + b1v, 0.f) * w31;
        }
        p0 += __shfl_xor_sync(0xFFFFFFFFu, p0, 1);
        p0 += __shfl_xor_sync(0xFFFFFFFFu, p0, 2);
        p1 += __shfl_xor_sync(0xFFFFFFFFu, p1, 1);
        p1 += __shfl_xor_sync(0xFFFFFFFFu, p1, 2);
        if (lt == 0) {
            sp[wm + lg +     64 * (wn >> 5)] = p0;
            sp[wm + lg + 8 + 64 * (wn >> 5)] = p1;
        }
        __syncthreads();
        if (tid < 64) {
            int r = t0 + tid;
            if (r < nrows) {
                float s = sp[tid] + sp[tid + 64] + sp[tid + 128] + sp[tid + 192] + __ldg(&b3[0]);
                pout[r] = 1.f / (1.f + expf(-s));
                if (logit_off > 0) pout[logit_off + r] = s;
            }
        }
    }
}

// ---------------- host ----------------
extern "C" void kernel_launch(void* const* d_in, const int* in_sizes, int n_in,
                              void* d_out, int out_size) {
    const float* feat    = (const float*)d_in[0];
    const int*   adj_dst = (const int*)  d_in[1];
    const int*   adj_src = (const int*)  d_in[2];
    const int*   cand_i  = (const int*)  d_in[3];
    const int*   cand_j  = (const int*)  d_in[4];
    const float* enc_W1 = (const float*)d_in[5];
    const float* enc_b1 = (const float*)d_in[6];
    const float* enc_W2 = (const float*)d_in[7];
    const float* enc_b2 = (const float*)d_in[8];
    const float* msg_W1 = (const float*)d_in[9];
    const float* msg_b1 = (const float*)d_in[10];
    const float* msg_W2 = (const float*)d_in[11];
    const float* msg_b2 = (const float*)d_in[12];
    const float* upd_W1 = (const float*)d_in[13];
    const float* upd_b1 = (const float*)d_in[14];
    const float* upd_W2 = (const float*)d_in[15];
    const float* upd_b2 = (const float*)d_in[16];
    const float* pred_W1 = (const float*)d_in[17];
    const float* pred_b1 = (const float*)d_in[18];
    const float* pred_W2 = (const float*)d_in[19];
    const float* pred_b2 = (const float*)d_in[20];
    const float* pred_W3 = (const float*)d_in[21];
    const float* pred_b3 = (const float*)d_in[22];

    int NE = in_sizes[0] / 64;
    int NA = in_sizes[1];
    int NC = in_sizes[3];
    if (NE > NE_MAX) NE = NE_MAX;

    float *Hagg, *bc;
    int* deg;
    u16 *eh, *el, *e2h, *e2l, *hh, *hl, *wh, *wl, *Pq, *Qq;
    cudaGetSymbolAddress((void**)&Pq,   g_Pq);
    cudaGetSymbolAddress((void**)&Qq,   g_Qq);
    cudaGetSymbolAddress((void**)&Hagg, g_agg);
    cudaGetSymbolAddress((void**)&deg,  g_deg);
    cudaGetSymbolAddress((void**)&bc,   g_bc);
    cudaGetSymbolAddress((void**)&eh,   g_eh);
    cudaGetSymbolAddress((void**)&el,   g_el);
    cudaGetSymbolAddress((void**)&e2h,  g_e2h);
    cudaGetSymbolAddress((void**)&e2l,  g_e2l);
    cudaGetSymbolAddress((void**)&hh,   g_hh);
    cudaGetSymbolAddress((void**)&hl,   g_hl);
    cudaGetSymbolAddress((void**)&wh,   g_wh);
    cudaGetSymbolAddress((void**)&wl,   g_wl);

    cudaFuncSetAttribute(gk_enc,   cudaFuncAttributeMaxDynamicSharedMemorySize, D_SMEM_BYTES);
    cudaFuncSetAttribute(gk_plain, cudaFuncAttributeMaxDynamicSharedMemorySize, SMEM_BYTES);
    cudaFuncSetAttribute(gk_dual,  cudaFuncAttributeMaxDynamicSharedMemorySize, D_SMEM_BYTES);
    cudaFuncSetAttribute(gk_upd,   cudaFuncAttributeMaxDynamicSharedMemorySize, D_SMEM_BYTES);
    cudaFuncSetAttribute(gk_pair,  cudaFuncAttributeMaxDynamicSharedMemorySize, SMEM_BYTES);

    cudaMemsetAsync(deg, 0, (size_t)NE * sizeof(int));
    deg_kernel<<<(NA + 255) / 256, 256>>>(adj_dst, NA, deg);

    // ---- weight prep ----
    PJobs pj;
    int cursor = 0, nj = 0;
    auto addjob = [&](const float* W, int ro, int K, int off) {
        pj.W[nj] = W; pj.rowoff[nj] = ro; pj.K[nj] = K; pj.off[nj] = off;
        pj.start[nj] = cursor; cursor += 128 * K; nj++;
    };
    addjob(enc_W1, 0, 64, OFF_ENC1);
    addjob(enc_W2, 0, 128, OFF_ENC2);
    for (int l = 0; l < 3; l++) {
        const float* mW1 = msg_W1 + (size_t)l * 2 * H * H;
        const float* uW1 = upd_W1 + (size_t)l * 2 * H * H;
        const float* uW2 = upd_W2 + (size_t)l * H * H;
        addjob(mW1, 0,   128, OFF_W1T(l));
        addjob(mW1, 128, 128, OFF_W1B(l));
        addjob(uW1, 0,   128, OFF_U1T(l));
        addjob(uW2, 0,   128, OFF_UW2(l));
    }
    addjob(pred_W1, 0,   128, OFF_P1T);
    addjob(pred_W1, 128, 128, OFF_P1B);
    addjob(pred_W2, 0,   128, OFF_P2);
    pj.njobs = nj; pj.total = cursor;
    prep_all<<<(cursor + 255) / 256, 256>>>(pj);
    compprep<<<195, 256>>>(upd_W1, msg_W2, msg_b2, upd_b1);

    int gNE = (NE + 63) / 64;
    int gNC = (NC + 63) / 64;
    int gE = gNE < 148 ? gNE : 148;
    int gC = gNC < 148 ? gNC : 148;

    // fused encoder
    gk_enc<<<gE, 512, D_SMEM_BYTES>>>(
        feat, wh + OFF_ENC1, wl + OFF_ENC1, wh + OFF_ENC2, wl + OFF_ENC2,
        enc_b1, enc_b2, eh, el, NE, gNE);

    u16 *ch = eh, *cl = el, *nh = e2h, *nl = e2l;
    for (int l = 0; l < 3; l++) {
        const float* mb1 = msg_b1 + (size_t)l * H;
        const float* ub2 = upd_b2 + (size_t)l * H;

        gk_dual<<<gE, 512, D_SMEM_BYTES>>>(
            ch, cl, wh + OFF_W1T(l), wl + OFF_W1T(l),
            wh + OFF_W1B(l), wl + OFF_W1B(l), Pq, Qq, NE, gNE);

        cudaMemsetAsync(Hagg, 0, (size_t)NE * H * sizeof(float));
        msum<<<(NA + 127) / 128, 256>>>(Pq, Qq, mb1, adj_dst, adj_src, Hagg, NA);

        gk_upd<<<gE, 512, D_SMEM_BYTES>>>(
            ch, cl, Hagg, Pq, Qq, mb1,
            wh + OFF_U1T(l), wl + OFF_U1T(l), wh + OFF_WC(l), wl + OFF_WC(l),
            bc + l * H, deg, hh, hl, NE, gNE);

        gk_plain<<<gE, 512, SMEM_BYTES>>>(
            hh, hl, wh + OFF_UW2(l), wl + OFF_UW2(l),
            ub2, nh, nl, NE, gNE);

        u16* t1 = ch; ch = nh; nh = t1;
        u16* t2 = cl; cl = nl; nl = t2;
    }

    gk_dual<<<gE, 512, D_SMEM_BYTES>>>(
        ch, cl, wh + OFF_P1T, wl + OFF_P1T,
        wh + OFF_P1B, wl + OFF_P1B, Pq, Qq, NE, gNE);
    int logit_off = (out_size >= 2 * NC) ? NC : -1;
    gk_pair<<<gC, 512, SMEM_BYTES>>>(
        Pq, Qq, cand_i, cand_j, wh + OFF_P2, wl + OFF_P2,
        pred_b1, pred_b2, pred_W3, pred_b3,
        (float*)d_out, NC, gNC, logit_off);
}

// round 17
// speedup vs baseline: 1.0168x; 1.0078x over previous
#include <cuda_runtime.h>
#include <cuda_bf16.h>
#include <cuda_fp16.h>
#include <stdint.h>
#include <math.h>

#define H 128
#define NE_MAX 50000

typedef unsigned int uint;
typedef unsigned short u16;

// ---------------- device scratch (allocation-free rule) ----------------
__device__ u16   g_eh [NE_MAX * H];
__device__ u16   g_el [NE_MAX * H];
__device__ u16   g_e2h[NE_MAX * H];
__device__ u16   g_e2l[NE_MAX * H];
__device__ u16   g_hh [NE_MAX * H];
__device__ u16   g_hl [NE_MAX * H];
__device__ u16   g_Pq [NE_MAX * H];      // fp16 P
__device__ u16   g_Qq [NE_MAX * H];      // fp16 Q
__device__ float g_agg[NE_MAX * H];
__device__ int   g_deg[NE_MAX];
__device__ float g_bc [3 * H];
#define WSCRATCH 368640
__device__ u16 g_wh[WSCRATCH];
__device__ u16 g_wl[WSCRATCH];

// transposed/split weight offsets (elements)
#define OFF_ENC1 0
#define OFF_ENC2 8192
#define OFF_L(l)   (24576 + (l) * 98304)
#define OFF_W1T(l) (OFF_L(l))
#define OFF_W1B(l) (OFF_L(l) + 16384)
#define OFF_WC(l)  (OFF_L(l) + 32768)
#define OFF_U1T(l) (OFF_L(l) + 49152)
#define OFF_UW2(l) (OFF_L(l) + 81920)
#define OFF_P1T 319488
#define OFF_P1B 335872
#define OFF_P2  352256

// ---- single-GEMM smem layout ----
#define WROW 68
#define WH_W 0
#define WL_W 8704
#define ABASE 17408
#define ABUF  8704
#define AHALF 4352
#define CTRL_W 34816
#define SMEM_WORDS 35104
#define SMEM_BYTES (SMEM_WORDS * 4)
// gk_pair staging (X,Y raw fp16 rows) lives in the second A buffer slot
#define PSTG (ABASE + ABUF)

// ---- dual-GEMM smem layout ----
#define D_W1H 0
#define D_W1L 8704
#define D_W2H 17408
#define D_W2L 26112
#define D_ABASE 34816
#define D_ABUF  8704
#define D_AHALF 4352
#define D_SMEM_WORDS 52224
#define D_SMEM_BYTES (D_SMEM_WORDS * 4)
// gk_enc staging (raw fp32 feat rows), appended after HID region
#define E_STG 52224
#define E_SMEM_WORDS 56576
#define E_SMEM_BYTES (E_SMEM_WORDS * 4)

// ---------------- helpers ----------------
__device__ __forceinline__ uint phi(float a, float b) {
    return (uint)__bfloat16_as_ushort(__float2bfloat16_rn(a))
         | ((uint)__bfloat16_as_ushort(__float2bfloat16_rn(b)) << 16);
}
__device__ __forceinline__ uint plo(float a, float b) {
    float ah = __bfloat162float(__float2bfloat16_rn(a));
    float bh = __bfloat162float(__float2bfloat16_rn(b));
    return phi(a - ah, b - bh);
}
__device__ __forceinline__ uint h2u(float a, float b) {
    __half2 h = __floats2half2_rn(a, b);
    return *(uint*)&h;
}
__device__ __forceinline__ float2 u2f(uint u) {
    return __half22float2(*(const __half2*)&u);
}
__device__ __forceinline__ uint smem_u32(const void* p) {
    uint a;
    asm("{ .reg .u64 t; cvta.to.shared.u64 t, %1; cvt.u32.u64 %0, t; }" : "=r"(a) : "l"(p));
    return a;
}
__device__ __forceinline__ void cpa16(uint dst, const void* src) {
    asm volatile("cp.async.cg.shared.global [%0], [%1], 16;" :: "r"(dst), "l"(src));
}
#define CPA_COMMIT() asm volatile("cp.async.commit_group;" ::: "memory")
#define CPA_WAIT(n)  asm volatile("cp.async.wait_group %0;" :: "n"(n) : "memory")

__device__ __forceinline__ void mma_bf(float* c, uint a0, uint a1, uint a2, uint a3,
                                       uint b0, uint b1) {
    asm volatile(
        "mma.sync.aligned.m16n8k16.row.col.f32.bf16.bf16.f32 "
        "{%0,%1,%2,%3},{%4,%5,%6,%7},{%8,%9},{%0,%1,%2,%3};"
        : "+f"(c[0]), "+f"(c[1]), "+f"(c[2]), "+f"(c[3])
        : "r"(a0), "r"(a1), "r"(a2), "r"(a3), "r"(b0), "r"(b1));
}
__device__ __forceinline__ void ldsm4(uint& r0, uint& r1, uint& r2, uint& r3, uint addr) {
    asm volatile("ldmatrix.sync.aligned.m8n8.x4.shared.b16 {%0,%1,%2,%3}, [%4];"
        : "=r"(r0), "=r"(r1), "=r"(r2), "=r"(r3) : "r"(addr));
}

// warp tile 16x32 via ldmatrix; 16 warps = 4(M) x 4(N); M-tile 64, N 128
template <int NK>
__device__ __forceinline__ void gemm_core_lm(uint sb, int aH, int aL, int wH, int wL,
                                             float acc[4][4], int wm, int wn, int lane) {
    const int l7 = lane & 7, lm = lane >> 3;
    const int radd = (lm & 1) * 8;
    const int koff = (lm >> 1) * 4;
    uint aBh  = sb + ((uint)(aH + (wm + l7 + radd) * WROW + koff) << 2);
    uint aBl  = sb + ((uint)(aL + (wm + l7 + radd) * WROW + koff) << 2);
    uint bBh0 = sb + ((uint)(wH + (wn + l7 + radd) * WROW + koff) << 2);
    uint bBl0 = sb + ((uint)(wL + (wn + l7 + radd) * WROW + koff) << 2);
    uint bBh1 = bBh0 + 16 * WROW * 4;
    uint bBl1 = bBl0 + 16 * WROW * 4;
#pragma unroll
    for (int ks = 0; ks < NK; ks++) {
        uint ko = ks * 32;
        uint ah0, ah1, ah2, ah3, al0, al1, al2, al3;
        ldsm4(ah0, ah1, ah2, ah3, aBh + ko);
        ldsm4(al0, al1, al2, al3, aBl + ko);
        uint p0, p1, p2, p3, q0, q1, q2, q3;
        ldsm4(p0, p1, p2, p3, bBh0 + ko);
        ldsm4(q0, q1, q2, q3, bBh1 + ko);
        uint u0, u1, u2, u3, v0, v1, v2, v3;
        ldsm4(u0, u1, u2, u3, bBl0 + ko);
        ldsm4(v0, v1, v2, v3, bBl1 + ko);
        mma_bf(acc[0], ah0, ah1, ah2, ah3, p0, p2);
        mma_bf(acc[1], ah0, ah1, ah2, ah3, p1, p3);
        mma_bf(acc[2], ah0, ah1, ah2, ah3, q0, q2);
        mma_bf(acc[3], ah0, ah1, ah2, ah3, q1, q3);
        mma_bf(acc[0], ah0, ah1, ah2, ah3, u0, u2);
        mma_bf(acc[1], ah0, ah1, ah2, ah3, u1, u3);
        mma_bf(acc[2], ah0, ah1, ah2, ah3, v0, v2);
        mma_bf(acc[3], ah0, ah1, ah2, ah3, v1, v3);
        mma_bf(acc[0], al0, al1, al2, al3, p0, p2);
        mma_bf(acc[1], al0, al1, al2, al3, p1, p3);
        mma_bf(acc[2], al0, al1, al2, al3, q0, q2);
        mma_bf(acc[3], al0, al1, al2, al3, q1, q3);
    }
}

template <int NK>
__device__ __forceinline__ void load_weights(uint* sm, int dH, int dL,
                                             const u16* Wth, const u16* Wtl, int tid) {
    const int nv = 128 * NK * 2;
    const uint4* sh = (const uint4*)Wth;
    const uint4* sl = (const uint4*)Wtl;
    for (int i = tid; i < nv; i += 512) {
        int n = i / (NK * 2), q = i % (NK * 2);
        *(uint4*)(sm + dH + n * WROW + q * 4) = sh[i];
        *(uint4*)(sm + dL + n * WROW + q * 4) = sl[i];
    }
}

// ---------------- small kernels ----------------
__global__ void deg_kernel(const int* __restrict__ dst, int na, int* __restrict__ deg) {
    int i = blockIdx.x * blockDim.x + threadIdx.x;
    if (i < na) atomicAdd(&deg[dst[i]], 1);
}

struct PJobs {
    const float* W[20];
    int rowoff[20], K[20], off[20], start[20];
    int njobs, total;
};
__global__ void prep_all(PJobs j) {
    int i = blockIdx.x * 256 + threadIdx.x;
    if (i >= j.total) return;
    int a = 0;
    while (a + 1 < j.njobs && i >= j.start[a + 1]) a++;
    int e = i - j.start[a];
    int K = j.K[a];
    int n = e / K, k = e % K;
    float v = j.W[a][(size_t)(j.rowoff[a] + k) * 128 + n];
    __nv_bfloat16 h = __float2bfloat16_rn(v);
    g_wh[j.off[a] + e] = __bfloat16_as_ushort(h);
    g_wl[j.off[a] + e] = __bfloat16_as_ushort(__float2bfloat16_rn(v - __bfloat162float(h)));
}

__global__ void compprep(const float* __restrict__ upd_W1,
                         const float* __restrict__ msg_W2,
                         const float* __restrict__ msg_b2,
                         const float* __restrict__ upd_b1) {
    int b = blockIdx.x;
    if (b < 192) {
        int l = b >> 6;
        int i = (b & 63) * 256 + threadIdx.x;
        int o = i & 127, h = i >> 7;
        const float* W2  = msg_W2 + (size_t)l * 16384;
        const float* U1b = upd_W1 + (size_t)l * 32768 + 16384;
        float s = 0.f;
        for (int a2 = 0; a2 < 128; a2++) s += W2[h * 128 + a2] * U1b[a2 * 128 + o];
        int li = OFF_WC(l) + o * 128 + h;
        __nv_bfloat16 hh = __float2bfloat16_rn(s);
        g_wh[li] = __bfloat16_as_ushort(hh);
        g_wl[li] = __bfloat16_as_ushort(__float2bfloat16_rn(s - __bfloat162float(hh)));
    } else if (b < 195) {
        int l = b - 192;
        int o = threadIdx.x;
        if (o < 128) {
            const float* U1b = upd_W1 + (size_t)l * 32768 + 16384;
            const float* b2  = msg_b2 + (size_t)l * 128;
            float s = upd_b1[l * 128 + o];
            for (int a2 = 0; a2 < 128; a2++) s += b2[a2] * U1b[a2 * 128 + o];
            g_bc[l * 128 + o] = s;
        }
    }
}

// pair hidden aggregation: Hagg[dst] += ReLU(P[dst] + Q[src] + b1)  (P,Q fp16)
__global__ __launch_bounds__(256) void msum(const u16* __restrict__ P,
                                            const u16* __restrict__ Q,
                                            const float* __restrict__ b1,
                                            const int* __restrict__ dst,
                                            const int* __restrict__ src,
                                            float* __restrict__ Hagg, int na) {
    int team = threadIdx.x >> 7, col = threadIdx.x & 127;
    int p0 = blockIdx.x * 128 + team * 64;
    if (p0 >= na) return;
    float bias = __ldg(&b1[col]);
    float sum = 0.f, pv = 0.f;
    int cur = -1;
    for (int base = 0; base < 64; base += 8) {
        int dd[8], ss[8];
#pragma unroll
        for (int j = 0; j < 8; j++) {
            int a = p0 + base + j;
            bool v = a < na;
            dd[j] = v ? __ldg(&dst[a]) : -1;
            ss[j] = v ? __ldg(&src[a]) : 0;
        }
        float qv[8];
#pragma unroll
        for (int j = 0; j < 8; j++)
            qv[j] = __half2float(((const __half*)Q)[(size_t)ss[j] * H + col]);
#pragma unroll
        for (int j = 0; j < 8; j++) {
            if (dd[j] != cur) {
                if (cur >= 0) atomicAdd(&Hagg[(size_t)cur * H + col], sum);
                cur = dd[j];
                sum = 0.f;
                if (cur >= 0)
                    pv = __half2float(((const __half*)P)[(size_t)cur * H + col]) + bias;
            }
            if (dd[j] >= 0) sum += fmaxf(pv + qv[j], 0.f);
        }
    }
    if (cur >= 0) atomicAdd(&Hagg[(size_t)cur * H + col], sum);
}

// ---------------- fused encoder (cp.async staged feat) ----------------
__global__ __launch_bounds__(512, 1)
void gk_enc(const float* __restrict__ feat,
            const u16* __restrict__ W1h_, const u16* __restrict__ W1l_,
            const u16* __restrict__ W2h_, const u16* __restrict__ W2l_,
            const float* __restrict__ b1, const float* __restrict__ b2,
            u16* __restrict__ obh, u16* __restrict__ obl,
            int nrows, int ntiles)
{
    extern __shared__ uint sm[];
    const int tid = threadIdx.x;
    const int lane = tid & 31, w = tid >> 5;
    const int wm = (w & 3) * 16, wn = (w >> 2) * 32;
    const uint sb = smem_u32(sm);
    const int HID = D_ABASE + D_ABUF;

    load_weights<4>(sm, D_W1H, D_W1L, W1h_, W1l_, tid);
    load_weights<8>(sm, D_W2H, D_W2L, W2h_, W2l_, tid);

    const int r8 = tid >> 3, c8 = tid & 7;
    const int lg = lane >> 2, lt = lane & 3;

    // prefetch raw fp32 feat rows into staging (each thread owns its chunk)
    auto pf = [&](int t) {
        int gr = t * 64 + r8;
        int rr = (gr < nrows) ? gr : 0;
        const char* s = (const char*)(feat + (size_t)rr * 64) + c8 * 32;
        uint d = sb + (uint)(E_STG + r8 * 68 + c8 * 8) * 4;
        cpa16(d, s);
        cpa16(d + 16, s + 16);
        CPA_COMMIT();
    };

    pf(blockIdx.x < ntiles ? blockIdx.x : 0);

    for (int t = blockIdx.x; t < ntiles; t += gridDim.x) {
        const int t0 = t * 64;
        CPA_WAIT(0);            // own staged chunk ready
        __syncthreads();        // previous tile done with A1/HID
        {   // convert staged fp32 -> bf16 hi/lo A1
            int base = D_ABASE + r8 * WROW + c8 * 4;
            int sgb = E_STG + r8 * 68 + c8 * 8;
#pragma unroll
            for (int q = 0; q < 2; q++) {
                float4 v = *(const float4*)(sm + sgb + q * 4);
                *(uint2*)(sm + base + 2 * q)           = make_uint2(phi(v.x, v.y), phi(v.z, v.w));
                *(uint2*)(sm + base + D_AHALF + 2 * q) = make_uint2(plo(v.x, v.y), plo(v.z, v.w));
            }
        }
        {   // prefetch next tile (overlaps with compute below)
            int tn = t + gridDim.x;
            pf(tn < ntiles ? tn : t);
        }
        __syncthreads();

        float acc[4][4];
#pragma unroll
        for (int nf = 0; nf < 4; nf++)
#pragma unroll
            for (int q = 0; q < 4; q++) acc[nf][q] = 0.f;
        gemm_core_lm<4>(sb, D_ABASE, D_ABASE + D_AHALF, D_W1H, D_W1L, acc, wm, wn, lane);

#pragma unroll
        for (int nf = 0; nf < 4; nf++) {
            int row = wm + lg;
            int col = wn + nf * 8 + lt * 2;
            float b0 = __ldg(&b1[col]), b1v = __ldg(&b1[col + 1]);
            float v0 = fmaxf(acc[nf][0] + b0, 0.f);
            float v1 = fmaxf(acc[nf][1] + b1v, 0.f);
            float v2 = fmaxf(acc[nf][2] + b0, 0.f);
            float v3 = fmaxf(acc[nf][3] + b1v, 0.f);
            int wi = col >> 1;
            sm[HID + row * WROW + wi]                 = phi(v0, v1);
            sm[HID + D_AHALF + row * WROW + wi]       = plo(v0, v1);
            sm[HID + (row + 8) * WROW + wi]           = phi(v2, v3);
            sm[HID + D_AHALF + (row + 8) * WROW + wi] = plo(v2, v3);
        }
        __syncthreads();

#pragma unroll
        for (int nf = 0; nf < 4; nf++)
#pragma unroll
            for (int q = 0; q < 4; q++) acc[nf][q] = 0.f;
        gemm_core_lm<8>(sb, HID, HID + D_AHALF, D_W2H, D_W2L, acc, wm, wn, lane);

#pragma unroll
        for (int nf = 0; nf < 4; nf++) {
            int row = wm + lg;
            int col = wn + nf * 8 + lt * 2;
            int g0 = t0 + row, g1 = g0 + 8;
            float b0 = __ldg(&b2[col]), b1v = __ldg(&b2[col + 1]);
            float v0 = acc[nf][0] + b0, v1 = acc[nf][1] + b1v;
            float v2 = acc[nf][2] + b0, v3 = acc[nf][3] + b1v;
            int wi = col >> 1;
            if (g0 < nrows) {
                ((uint*)obh)[(size_t)g0 * 64 + wi] = phi(v0, v1);
                ((uint*)obl)[(size_t)g0 * 64 + wi] = plo(v0, v1);
            }
            if (g1 < nrows) {
                ((uint*)obh)[(size_t)g1 * 64 + wi] = phi(v2, v3);
                ((uint*)obl)[(size_t)g1 * 64 + wi] = plo(v2, v3);
            }
        }
    }
}

// ---------------- single GEMM (bf16 in, cp.async double-buffer), bias+ReLU -> bf16 ----------------
__global__ __launch_bounds__(512, 1)
void gk_plain(const u16* __restrict__ Aph, const u16* __restrict__ Apl,
              const u16* __restrict__ Wth, const u16* __restrict__ Wtl,
              const float* __restrict__ bias,
              u16* __restrict__ obh, u16* __restrict__ obl,
              int nrows, int ntiles)
{
    extern __shared__ uint sm[];
    const int tid = threadIdx.x;
    const int lane = tid & 31, w = tid >> 5;
    const int wm = (w & 3) * 16, wn = (w >> 2) * 32;
    const uint sb = smem_u32(sm);

    load_weights<8>(sm, WH_W, WL_W, Wth, Wtl, tid);

    const int r8 = tid >> 3, c8 = tid & 7;

    auto fill_async = [&](int t, int p) {
        int gr = t * 64 + r8;
        int rr = (gr < nrows) ? gr : 0;
        const char* shp = (const char*)(Aph + (size_t)rr * H) + c8 * 16;
        const char* slp = (const char*)(Apl + (size_t)rr * H) + c8 * 16;
        uint dh = sb + (ABASE + p * ABUF + r8 * WROW + c8 * 4) * 4;
        uint dl = dh + AHALF * 4;
        cpa16(dh, shp);        cpa16(dh + 128, shp + 128);
        cpa16(dl, slp);        cpa16(dl + 128, slp + 128);
        CPA_COMMIT();
    };

    int p = 0;
    fill_async(blockIdx.x < ntiles ? blockIdx.x : 0, 0);

    for (int t = blockIdx.x; t < ntiles; t += gridDim.x) {
        __syncthreads();
        int tn = t + gridDim.x;
        fill_async(tn < ntiles ? tn : t, p ^ 1);
        CPA_WAIT(1);
        __syncthreads();

        float acc[4][4];
#pragma unroll
        for (int nf = 0; nf < 4; nf++)
#pragma unroll
            for (int q = 0; q < 4; q++) acc[nf][q] = 0.f;
        int aH = ABASE + p * ABUF;
        gemm_core_lm<8>(sb, aH, aH + AHALF, WH_W, WL_W, acc, wm, wn, lane);

        const int t0 = t * 64;
        const int lg = lane >> 2, lt = lane & 3;
#pragma unroll
        for (int nf = 0; nf < 4; nf++) {
            int row = wm + lg;
            int col = wn + nf * 8 + lt * 2;
            int g0 = t0 + row, g1 = g0 + 8;
            float b0 = __ldg(&bias[col]), b1v = __ldg(&bias[col + 1]);
            float v0 = fmaxf(acc[nf][0] + b0, 0.f);
            float v1 = fmaxf(acc[nf][1] + b1v, 0.f);
            float v2 = fmaxf(acc[nf][2] + b0, 0.f);
            float v3 = fmaxf(acc[nf][3] + b1v, 0.f);
            int wi = col >> 1;
            if (g0 < nrows) {
                ((uint*)obh)[(size_t)g0 * 64 + wi] = phi(v0, v1);
                ((uint*)obl)[(size_t)g0 * 64 + wi] = plo(v0, v1);
            }
            if (g1 < nrows) {
                ((uint*)obh)[(size_t)g1 * 64 + wi] = phi(v2, v3);
                ((uint*)obl)[(size_t)g1 * 64 + wi] = plo(v2, v3);
            }
        }
        p ^= 1;
    }
}

// ---------------- dual GEMM, shared A: out1 = A@W1, out2 = A@W2 -> fp16 ----------------
__global__ __launch_bounds__(512, 1)
void gk_dual(const u16* __restrict__ Aph, const u16* __restrict__ Apl,
             const u16* __restrict__ W1h_, const u16* __restrict__ W1l_,
             const u16* __restrict__ W2h_, const u16* __restrict__ W2l_,
             u16* __restrict__ out1, u16* __restrict__ out2,
             int nrows, int ntiles)
{
    extern __shared__ uint sm[];
    const int tid = threadIdx.x;
    const int lane = tid & 31, w = tid >> 5;
    const int wm = (w & 3) * 16, wn = (w >> 2) * 32;
    const uint sb = smem_u32(sm);

    load_weights<8>(sm, D_W1H, D_W1L, W1h_, W1l_, tid);
    load_weights<8>(sm, D_W2H, D_W2L, W2h_, W2l_, tid);

    const int r8 = tid >> 3, c8 = tid & 7;
    auto fill_async = [&](int t, int p) {
        int gr = t * 64 + r8;
        int rr = (gr < nrows) ? gr : 0;
        const char* shp = (const char*)(Aph + (size_t)rr * H) + c8 * 16;
        const char* slp = (const char*)(Apl + (size_t)rr * H) + c8 * 16;
        uint dh = sb + (D_ABASE + p * D_ABUF + r8 * WROW + c8 * 4) * 4;
        uint dl = dh + D_AHALF * 4;
        cpa16(dh, shp);        cpa16(dh + 128, shp + 128);
        cpa16(dl, slp);        cpa16(dl + 128, slp + 128);
        CPA_COMMIT();
    };

    int p = 0;
    fill_async(blockIdx.x < ntiles ? blockIdx.x : 0, 0);

    for (int t = blockIdx.x; t < ntiles; t += gridDim.x) {
        __syncthreads();
        int tn = t + gridDim.x;
        fill_async(tn < ntiles ? tn : t, p ^ 1);
        CPA_WAIT(1);
        __syncthreads();

        int aH = D_ABASE + p * D_ABUF;
        float acc1[4][4], acc2[4][4];
#pragma unroll
        for (int nf = 0; nf < 4; nf++)
#pragma unroll
            for (int q = 0; q < 4; q++) { acc1[nf][q] = 0.f; acc2[nf][q] = 0.f; }
        gemm_core_lm<8>(sb, aH, aH + D_AHALF, D_W1H, D_W1L, acc1, wm, wn, lane);
        gemm_core_lm<8>(sb, aH, aH + D_AHALF, D_W2H, D_W2L, acc2, wm, wn, lane);

        const int t0 = t * 64;
        const int lg = lane >> 2, lt = lane & 3;
#pragma unroll
        for (int nf = 0; nf < 4; nf++) {
            int row = wm + lg;
            int col = wn + nf * 8 + lt * 2;
            int g0 = t0 + row, g1 = g0 + 8;
            int wi = col >> 1;
            if (g0 < nrows) {
                ((uint*)out1)[(size_t)g0 * 64 + wi] = h2u(acc1[nf][0], acc1[nf][1]);
                ((uint*)out2)[(size_t)g0 * 64 + wi] = h2u(acc2[nf][0], acc2[nf][1]);
            }
            if (g1 < nrows) {
                ((uint*)out1)[(size_t)g1 * 64 + wi] = h2u(acc1[nf][2], acc1[nf][3]);
                ((uint*)out2)[(size_t)g1 * 64 + wi] = h2u(acc2[nf][2], acc2[nf][3]);
            }
        }
        p ^= 1;
    }
}

// ---------------- update fused: hid = ReLU(e@U1T + (Hagg*inv_deg)@WC + bias) -> bf16 ----------------
// deg==0 rows: A2 = ReLU(P+Q+mb1) inline (replaces fixup kernel)
__global__ __launch_bounds__(512, 1)
void gk_upd(const u16* __restrict__ Aph, const u16* __restrict__ Apl,
            const float* __restrict__ Hagg,
            const u16* __restrict__ Pq, const u16* __restrict__ Qq,
            const float* __restrict__ mb1,
            const u16* __restrict__ W1h_, const u16* __restrict__ W1l_,
            const u16* __restrict__ W2h_, const u16* __restrict__ W2l_,
            const float* __restrict__ bias, const int* __restrict__ deg,
            u16* __restrict__ obh, u16* __restrict__ obl,
            int nrows, int ntiles)
{
    extern __shared__ uint sm[];
    const int tid = threadIdx.x;
    const int lane = tid & 31, w = tid >> 5;
    const int wm = (w & 3) * 16, wn = (w >> 2) * 32;
    const uint sb = smem_u32(sm);

    load_weights<8>(sm, D_W1H, D_W1L, W1h_, W1l_, tid);
    load_weights<8>(sm, D_W2H, D_W2L, W2h_, W2l_, tid);

    const int r8 = tid >> 3, c8 = tid & 7;

    for (int t = blockIdx.x; t < ntiles; t += gridDim.x) {
        const int t0 = t * 64;
        int gr = t0 + r8;
        int rr = (gr < nrows) ? gr : 0;
        __syncthreads();
        {   // A1: e via cp.async
            const char* shp = (const char*)(Aph + (size_t)rr * H) + c8 * 16;
            const char* slp = (const char*)(Apl + (size_t)rr * H) + c8 * 16;
            uint dh = sb + (D_ABASE + r8 * WROW + c8 * 4) * 4;
            uint dl = dh + D_AHALF * 4;
            cpa16(dh, shp);        cpa16(dh + 128, shp + 128);
            cpa16(dl, slp);        cpa16(dl + 128, slp + 128);
            CPA_COMMIT();
        }
        {   // A2: Hagg * inv_deg  (or iso: ReLU(P+Q+mb1))
            int d = deg[rr];
            int base = D_ABASE + D_ABUF + r8 * WROW + c8 * 8;
            float vals[16];
            if (d == 0) {
                const uint4* pp = (const uint4*)(Pq + (size_t)rr * H + c8 * 16);
                const uint4* qq = (const uint4*)(Qq + (size_t)rr * H + c8 * 16);
#pragma unroll
                for (int q = 0; q < 2; q++) {
                    uint4 xv = pp[q], yv = qq[q];
                    uint xu[4] = {xv.x, xv.y, xv.z, xv.w};
                    uint yu[4] = {yv.x, yv.y, yv.z, yv.w};
#pragma unroll
                    for (int k = 0; k < 4; k++) {
                        float2 fx = u2f(xu[k]), fy = u2f(yu[k]);
                        int c = c8 * 16 + q * 8 + k * 2;
                        vals[q * 8 + k * 2]     = fmaxf(fx.x + fy.x + __ldg(&mb1[c]),     0.f);
                        vals[q * 8 + k * 2 + 1] = fmaxf(fx.y + fy.y + __ldg(&mb1[c + 1]), 0.f);
                    }
                }
            } else {
                float sc = 1.f / (d > 1 ? (float)d : 1.f);
                const float4* s = (const float4*)(Hagg + (size_t)rr * H) + c8 * 4;
#pragma unroll
                for (int q = 0; q < 4; q++) {
                    float4 v = s[q];
                    vals[4*q] = v.x*sc; vals[4*q+1] = v.y*sc; vals[4*q+2] = v.z*sc; vals[4*q+3] = v.w*sc;
                }
            }
#pragma unroll
            for (int q = 0; q < 4; q++) {
                *(uint2*)(sm + base + 2 * q) =
                    make_uint2(phi(vals[4*q], vals[4*q+1]), phi(vals[4*q+2], vals[4*q+3]));
                *(uint2*)(sm + base + D_AHALF + 2 * q) =
                    make_uint2(plo(vals[4*q], vals[4*q+1]), plo(vals[4*q+2], vals[4*q+3]));
            }
        }
        CPA_WAIT(0);
        __syncthreads();

        float acc[4][4];
#pragma unroll
        for (int nf = 0; nf < 4; nf++)
#pragma unroll
            for (int q = 0; q < 4; q++) acc[nf][q] = 0.f;
        gemm_core_lm<8>(sb, D_ABASE, D_ABASE + D_AHALF, D_W1H, D_W1L, acc, wm, wn, lane);
        gemm_core_lm<8>(sb, D_ABASE + D_ABUF, D_ABASE + D_ABUF + D_AHALF, D_W2H, D_W2L, acc, wm, wn, lane);

        const int lg = lane >> 2, lt = lane & 3;
#pragma unroll
        for (int nf = 0; nf < 4; nf++) {
            int row = wm + lg;
            int col = wn + nf * 8 + lt * 2;
            int g0 = t0 + row, g1 = g0 + 8;
            float b0 = __ldg(&bias[col]), b1v = __ldg(&bias[col + 1]);
            float v0 = fmaxf(acc[nf][0] + b0, 0.f);
            float v1 = fmaxf(acc[nf][1] + b1v, 0.f);
            float v2 = fmaxf(acc[nf][2] + b0, 0.f);
            float v3 = fmaxf(acc[nf][3] + b1v, 0.f);
            int wi = col >> 1;
            if (g0 < nrows) {
                ((uint*)obh)[(size_t)g0 * 64 + wi] = phi(v0, v1);
                ((uint*)obl)[(size_t)g0 * 64 + wi] = plo(v0, v1);
            }
            if (g1 < nrows) {
                ((uint*)obh)[(size_t)g1 * 64 + wi] = phi(v2, v3);
                ((uint*)obl)[(size_t)g1 * 64 + wi] = plo(v2, v3);
            }
        }
    }
}

// ---------------- pairsum GEMM + predictor epilogue (X,Y fp16, cp.async staged) ----------------
__global__ __launch_bounds__(512, 1)
void gk_pair(const u16* __restrict__ X, const u16* __restrict__ Y,
             const int* __restrict__ idx0, const int* __restrict__ idx1,
             const u16* __restrict__ Wth, const u16* __restrict__ Wtl,
             const float* __restrict__ b1, const float* __restrict__ b2,
             const float* __restrict__ W3, const float* __restrict__ b3,
             float* __restrict__ pout,
             int nrows, int ntiles, int logit_off)
{
    extern __shared__ uint sm[];
    float* sp = (float*)(sm + CTRL_W);

    const int tid = threadIdx.x;
    const int lane = tid & 31, w = tid >> 5;
    const int wm = (w & 3) * 16, wn = (w >> 2) * 32;
    const uint sb = smem_u32(sm);

    load_weights<8>(sm, WH_W, WL_W, Wth, Wtl, tid);

    const int r8 = tid >> 3, c8 = tid & 7;

    // prefetch gathered X/Y rows (raw fp16) into staging; each thread owns its chunk
    auto pf = [&](int t) {
        int gr = t * 64 + r8;
        int rr = (gr < nrows) ? gr : 0;
        int i0 = __ldg(&idx0[rr]);
        int i1 = __ldg(&idx1[rr]);
        const char* xs = (const char*)(X + (size_t)i0 * H) + c8 * 32;
        const char* ys = (const char*)(Y + (size_t)i1 * H) + c8 * 32;
        uint dx = sb + (uint)(PSTG + r8 * 68 + c8 * 8) * 4;
        uint dy = dx + 4352 * 4;
        cpa16(dx, xs);  cpa16(dx + 16, xs + 16);
        cpa16(dy, ys);  cpa16(dy + 16, ys + 16);
        CPA_COMMIT();
    };

    pf(blockIdx.x < ntiles ? blockIdx.x : 0);

    for (int t = blockIdx.x; t < ntiles; t += gridDim.x) {
        const int t0 = t * 64;
        CPA_WAIT(0);            // own staged X/Y ready
        __syncthreads();        // prev tile done with A / sp
        {   // hid = ReLU(X + Y + b1) from staging, split hi/lo -> A
            int ch = c8 * 16;
            int sgx = PSTG + r8 * 68 + c8 * 8;
            int base = ABASE + r8 * WROW + c8 * 8;
#pragma unroll
            for (int q = 0; q < 2; q++) {
                uint4 xv = *(const uint4*)(sm + sgx + q * 4);
                uint4 yv = *(const uint4*)(sm + sgx + 4352 + q * 4);
                uint xu[4] = {xv.x, xv.y, xv.z, xv.w};
                uint yu[4] = {yv.x, yv.y, yv.z, yv.w};
                float v[8];
#pragma unroll
                for (int k = 0; k < 4; k++) {
                    float2 fx = u2f(xu[k]), fy = u2f(yu[k]);
                    int c = ch + q * 8 + k * 2;
                    v[2*k]     = fmaxf(fx.x + fy.x + __ldg(&b1[c]),     0.f);
                    v[2*k + 1] = fmaxf(fx.y + fy.y + __ldg(&b1[c + 1]), 0.f);
                }
#pragma unroll
                for (int k = 0; k < 4; k++) {
                    sm[base + q * 4 + k]         = phi(v[2*k], v[2*k+1]);
                    sm[base + AHALF + q * 4 + k] = plo(v[2*k], v[2*k+1]);
                }
            }
        }
        {   // prefetch next tile (idx load + gather overlapped with mma below)
            int tn = t + gridDim.x;
            pf(tn < ntiles ? tn : t);
        }
        __syncthreads();

        float acc[4][4];
#pragma unroll
        for (int nf = 0; nf < 4; nf++)
#pragma unroll
            for (int q = 0; q < 4; q++) acc[nf][q] = 0.f;
        gemm_core_lm<8>(sb, ABASE, ABASE + AHALF, WH_W, WL_W, acc, wm, wn, lane);

        const int lg = lane >> 2, lt = lane & 3;
        float p0 = 0.f, p1 = 0.f;
#pragma unroll
        for (int nf = 0; nf < 4; nf++) {
            int col = wn + nf * 8 + lt * 2;
            float b0 = __ldg(&b2[col]), b1v = __ldg(&b2[col + 1]);
            float w30 = __ldg(&W3[col]), w31 = __ldg(&W3[col + 1]);
            p0 += fmaxf(acc[nf][0] + b0, 0.f) * w30
                + fmaxf(acc[nf][1] + b1v, 0.f) * w31;
            p1 += fmaxf(acc[nf][2] + b0, 0.f) * w30
                + fmaxf(acc[nf][3] + b1v, 0.f) * w31;
        }
        p0 += __shfl_xor_sync(0xFFFFFFFFu, p0, 1);
        p0 += __shfl_xor_sync(0xFFFFFFFFu, p0, 2);
        p1 += __shfl_xor_sync(0xFFFFFFFFu, p1, 1);
        p1 += __shfl_xor_sync(0xFFFFFFFFu, p1, 2);
        if (lt == 0) {
            sp[wm + lg +     64 * (wn >> 5)] = p0;
            sp[wm + lg + 8 + 64 * (wn >> 5)] = p1;
        }
        __syncthreads();
        if (tid < 64) {
            int r = t0 + tid;
            if (r < nrows) {
                float s = sp[tid] + sp[tid + 64] + sp[tid + 128] + sp[tid + 192] + __ldg(&b3[0]);
                pout[r] = 1.f / (1.f + expf(-s));
                if (logit_off > 0) pout[logit_off + r] = s;
            }
        }
    }
}

// ---------------- host ----------------
extern "C" void kernel_launch(void* const* d_in, const int* in_sizes, int n_in,
                              void* d_out, int out_size) {
    const float* feat    = (const float*)d_in[0];
    const int*   adj_dst = (const int*)  d_in[1];
    const int*   adj_src = (const int*)  d_in[2];
    const int*   cand_i  = (const int*)  d_in[3];
    const int*   cand_j  = (const int*)  d_in[4];
    const float* enc_W1 = (const float*)d_in[5];
    const float* enc_b1 = (const float*)d_in[6];
    const float* enc_W2 = (const float*)d_in[7];
    const float* enc_b2 = (const float*)d_in[8];
    const float* msg_W1 = (const float*)d_in[9];
    const float* msg_b1 = (const float*)d_in[10];
    const float* msg_W2 = (const float*)d_in[11];
    const float* msg_b2 = (const float*)d_in[12];
    const float* upd_W1 = (const float*)d_in[13];
    const float* upd_b1 = (const float*)d_in[14];
    const float* upd_W2 = (const float*)d_in[15];
    const float* upd_b2 = (const float*)d_in[16];
    const float* pred_W1 = (const float*)d_in[17];
    const float* pred_b1 = (const float*)d_in[18];
    const float* pred_W2 = (const float*)d_in[19];
    const float* pred_b2 = (const float*)d_in[20];
    const float* pred_W3 = (const float*)d_in[21];
    const float* pred_b3 = (const float*)d_in[22];

    int NE = in_sizes[0] / 64;
    int NA = in_sizes[1];
    int NC = in_sizes[3];
    if (NE > NE_MAX) NE = NE_MAX;

    float *Hagg, *bc;
    int* deg;
    u16 *eh, *el, *e2h, *e2l, *hh, *hl, *wh, *wl, *Pq, *Qq;
    cudaGetSymbolAddress((void**)&Pq,   g_Pq);
    cudaGetSymbolAddress((void**)&Qq,   g_Qq);
    cudaGetSymbolAddress((void**)&Hagg, g_agg);
    cudaGetSymbolAddress((void**)&deg,  g_deg);
    cudaGetSymbolAddress((void**)&bc,   g_bc);
    cudaGetSymbolAddress((void**)&eh,   g_eh);
    cudaGetSymbolAddress((void**)&el,   g_el);
    cudaGetSymbolAddress((void**)&e2h,  g_e2h);
    cudaGetSymbolAddress((void**)&e2l,  g_e2l);
    cudaGetSymbolAddress((void**)&hh,   g_hh);
    cudaGetSymbolAddress((void**)&hl,   g_hl);
    cudaGetSymbolAddress((void**)&wh,   g_wh);
    cudaGetSymbolAddress((void**)&wl,   g_wl);

    cudaFuncSetAttribute(gk_enc,   cudaFuncAttributeMaxDynamicSharedMemorySize, E_SMEM_BYTES);
    cudaFuncSetAttribute(gk_plain, cudaFuncAttributeMaxDynamicSharedMemorySize, SMEM_BYTES);
    cudaFuncSetAttribute(gk_dual,  cudaFuncAttributeMaxDynamicSharedMemorySize, D_SMEM_BYTES);
    cudaFuncSetAttribute(gk_upd,   cudaFuncAttributeMaxDynamicSharedMemorySize, D_SMEM_BYTES);
    cudaFuncSetAttribute(gk_pair,  cudaFuncAttributeMaxDynamicSharedMemorySize, SMEM_BYTES);

    cudaMemsetAsync(deg, 0, (size_t)NE * sizeof(int));
    deg_kernel<<<(NA + 255) / 256, 256>>>(adj_dst, NA, deg);

    // ---- weight prep ----
    PJobs pj;
    int cursor = 0, nj = 0;
    auto addjob = [&](const float* W, int ro, int K, int off) {
        pj.W[nj] = W; pj.rowoff[nj] = ro; pj.K[nj] = K; pj.off[nj] = off;
        pj.start[nj] = cursor; cursor += 128 * K; nj++;
    };
    addjob(enc_W1, 0, 64, OFF_ENC1);
    addjob(enc_W2, 0, 128, OFF_ENC2);
    for (int l = 0; l < 3; l++) {
        const float* mW1 = msg_W1 + (size_t)l * 2 * H * H;
        const float* uW1 = upd_W1 + (size_t)l * 2 * H * H;
        const float* uW2 = upd_W2 + (size_t)l * H * H;
        addjob(mW1, 0,   128, OFF_W1T(l));
        addjob(mW1, 128, 128, OFF_W1B(l));
        addjob(uW1, 0,   128, OFF_U1T(l));
        addjob(uW2, 0,   128, OFF_UW2(l));
    }
    addjob(pred_W1, 0,   128, OFF_P1T);
    addjob(pred_W1, 128, 128, OFF_P1B);
    addjob(pred_W2, 0,   128, OFF_P2);
    pj.njobs = nj; pj.total = cursor;
    prep_all<<<(cursor + 255) / 256, 256>>>(pj);
    compprep<<<195, 256>>>(upd_W1, msg_W2, msg_b2, upd_b1);

    int gNE = (NE + 63) / 64;
    int gNC = (NC + 63) / 64;
    int gE = gNE < 148 ? gNE : 148;
    int gC = gNC < 148 ? gNC : 148;

    // fused encoder
    gk_enc<<<gE, 512, E_SMEM_BYTES>>>(
        feat, wh + OFF_ENC1, wl + OFF_ENC1, wh + OFF_ENC2, wl + OFF_ENC2,
        enc_b1, enc_b2, eh, el, NE, gNE);

    u16 *ch = eh, *cl = el, *nh = e2h, *nl = e2l;
    for (int l = 0; l < 3; l++) {
        const float* mb1 = msg_b1 + (size_t)l * H;
        const float* ub2 = upd_b2 + (size_t)l * H;

        gk_dual<<<gE, 512, D_SMEM_BYTES>>>(
            ch, cl, wh + OFF_W1T(l), wl + OFF_W1T(l),
            wh + OFF_W1B(l), wl + OFF_W1B(l), Pq, Qq, NE, gNE);

        cudaMemsetAsync(Hagg, 0, (size_t)NE * H * sizeof(float));
        msum<<<(NA + 127) / 128, 256>>>(Pq, Qq, mb1, adj_dst, adj_src, Hagg, NA);

        gk_upd<<<gE, 512, D_SMEM_BYTES>>>(
            ch, cl, Hagg, Pq, Qq, mb1,
            wh + OFF_U1T(l), wl + OFF_U1T(l), wh + OFF_WC(l), wl + OFF_WC(l),
            bc + l * H, deg, hh, hl, NE, gNE);

        gk_plain<<<gE, 512, SMEM_BYTES>>>(
            hh, hl, wh + OFF_UW2(l), wl + OFF_UW2(l),
            ub2, nh, nl, NE, gNE);

        u16* t1 = ch; ch = nh; nh = t1;
        u16* t2 = cl; cl = nl; nl = t2;
    }

    gk_dual<<<gE, 512, D_SMEM_BYTES>>>(
        ch, cl, wh + OFF_P1T, wl + OFF_P1T,
        wh + OFF_P1B, wl + OFF_P1B, Pq, Qq, NE, gNE);
    int logit_off = (out_size >= 2 * NC) ? NC : -1;
    gk_pair<<<gC, 512, SMEM_BYTES>>>(
        Pq, Qq, cand_i, cand_j, wh + OFF_P2, wl + OFF_P2,
        pred_b1, pred_b2, pred_W3, pred_b3,
        (float*)d_out, NC, gNC, logit_off);
}